// round 9
// baseline (speedup 1.0000x reference)
#include <cuda_runtime.h>
#include <math.h>

#define P       512
#define K_MAX   16
#define NM      (K_MAX + 1)
#define M_CAP   65536
#define NCH_MAX 256
#define NB      64
#define NSTEP   (P / NB)      // 8
#define NSLICE  3
#define DP      68
#define NCTA    15            // CTAs per matrix in persistent chol

#define FT_SMEM_BYTES (4 * NB * DP * 4)   // 69632 B

typedef unsigned long long ull;

// ---------------- f32x2 packed helpers (Blackwell sm_103a) -----------------
__device__ __forceinline__ ull ffma2(ull a, ull b, ull c) {
    ull d;
    asm("fma.rn.f32x2 %0, %1, %2, %3;" : "=l"(d) : "l"(a), "l"(b), "l"(c));
    return d;
}
__device__ __forceinline__ ull dup2(float x) {
    ull r; unsigned xb = __float_as_uint(x);
    asm("mov.b64 %0, {%1, %2};" : "=l"(r) : "r"(xb), "r"(xb));
    return r;
}
__device__ __forceinline__ ull pack2(float lo, float hi) {
    ull r;
    asm("mov.b64 %0, {%1, %2};" : "=l"(r) : "f"(lo), "f"(hi));
    return r;
}
__device__ __forceinline__ float2 unpk2(ull v) {
    float2 r;
    asm("mov.b64 {%0, %1}, %2;" : "=f"(r.x), "=f"(r.y) : "l"(v));
    return r;
}

// ---------------- device scratch -------------------------------------------
__device__ int    d_cnt[K_MAX];
__device__ int    d_kval;
__device__ int    d_idx[M_CAP];
__device__ int    d_bh[NCH_MAX][K_MAX];
__device__ int    d_boff[NCH_MAX][K_MAX];
__device__ int    d_cstart[K_MAX];
__device__ int    d_lbar;                 // labels-kernel barrier (reset by chol)
__device__ int    d_bar[NM];              // per-matrix chol barriers
__device__ int    d_done;                 // matrices-finished counter
__device__ float  d_Gk[NSLICE][K_MAX][P * P];
__device__ float  d_A[NM][P * P];
__device__ float  d_Dinv[2][NM][NB * DP];
__device__ double d_hldd[NM];

// ---------------- global barrier for k_labels ------------------------------
__device__ __forceinline__ void gbar(int nb, int ep) {
    __syncthreads();
    __threadfence();
    if (threadIdx.x == 0) {
        atomicAdd(&d_lbar, 1);
        while (atomicAdd(&d_lbar, 0) < nb * ep) __nanosleep(64);
        __threadfence();
    }
    __syncthreads();
}

// ---------------- per-matrix barrier for k_chol ----------------------------
__device__ __forceinline__ void mbar(int mb, int target) {
    __syncthreads();
    __threadfence();
    if (threadIdx.x == 0) {
        atomicAdd(&d_bar[mb], 1);
        while (atomicAdd(&d_bar[mb], 0) < target) __nanosleep(64);
        __threadfence();
    }
    __syncthreads();
}

// ------- k_labels: dtype detect + hist + scan + stable scatter (1 launch) --
__global__ __launch_bounds__(256) void k_labels(const void* __restrict__ Y,
                                                const int* ncls, int m,
                                                int nchunk) {
    __shared__ int sh[K_MAX];
    __shared__ int swh[8 * K_MAX];
    __shared__ int nzf;
    int tid = threadIdx.x;
    int b = blockIdx.x;
    if (tid == 0) nzf = 0;
    if (tid < K_MAX) sh[tid] = 0;
    __syncthreads();

    // dtype detect: every block scans the same first <=4KB (L2-cached)
    int lim = m / 2; if (lim > 512) lim = 512;
    int found = 0;
    for (int i = tid; i < lim; i += 256)
        if (((const int*)Y)[2 * i + 1] != 0) found = 1;
    if (__any_sync(0xffffffffu, found)) {
        if ((tid & 31) == 0) atomicOr(&nzf, 1);
    }
    __syncthreads();
    int is64 = nzf ? 0 : 1;

    int i = b * 256 + tid;
    int c = -1;
    if (i < m) {
        c = is64 ? (int)((const long long*)Y)[i] : ((const int*)Y)[i];
        if (c < 0 || c >= K_MAX) c = 0;
        atomicAdd(&sh[c], 1);
    }
    __syncthreads();
    if (tid < K_MAX) d_bh[b][tid] = sh[tid];

    gbar(nchunk, 1);

    if (b == 0) {
        if (tid < K_MAX) {
            int run = 0;
            for (int bb = 0; bb < nchunk; bb++) {
                d_boff[bb][tid] = run;
                run += d_bh[bb][tid];
            }
            d_cnt[tid] = run;
            sh[tid] = run;
        }
        __syncthreads();
        if (tid == 0) {
            int run = 0;
            for (int cc = 0; cc < K_MAX; cc++) {
                d_cstart[cc] = run;
                run += sh[cc];
            }
            int k = ncls ? *ncls : 10;
            if (k < 1) k = 1;
            if (k > K_MAX) k = K_MAX;
            d_kval = k;
            d_done = 0;
        }
        if (tid < NM) { d_hldd[tid] = 0.0; d_bar[tid] = 0; }
    }

    gbar(nchunk, 2);

    // stable scatter: warp match ranks + per-warp histogram prefix
    if (tid < 8 * K_MAX) swh[tid] = 0;
    __syncthreads();
    int lane = tid & 31, w = tid >> 5;
    unsigned mask = __match_any_sync(0xffffffffu, c);
    int rin = __popc(mask & ((1u << lane) - 1u));
    int leader = __ffs(mask) - 1;
    if (c >= 0 && lane == leader) swh[w * K_MAX + c] = __popc(mask);
    __syncthreads();
    if (c >= 0) {
        int pre = 0;
        for (int w2 = 0; w2 < w; w2++) pre += swh[w2 * K_MAX + c];
        d_idx[d_cstart[c] + d_boff[b][c] + pre + rin] = i;
    }
}

// ------- per-class Gram: dense gather over sorted class range --------------
__global__ __launch_bounds__(256) void k_gram(const float* __restrict__ X,
                                              int p) {
    int c = blockIdx.y;
    if (c >= d_kval) return;
    int tile = blockIdx.x;
    int ti = 0;
    while ((ti + 1) * (ti + 2) / 2 <= tile) ti++;
    int tj = tile - ti * (ti + 1) / 2;
    int a0 = ti * 128, b0 = tj * 128;
    int z = blockIdx.z;
    int cstart = d_cstart[c], ccnt = d_cnt[c];
    int sb = (int)((long long)ccnt * z / NSLICE);
    int se = (int)((long long)ccnt * (z + 1) / NSLICE);

    __shared__ __align__(16) float sA[32][132];
    __shared__ __align__(16) float sB[32][132];
    __shared__ int sidx[32];

    int tid = threadIdx.x;
    int tx = tid & 15, ty = tid >> 4;
    int lt = tid >> 3, lc = tid & 7;

    ull acc2[8][4];
#pragma unroll
    for (int i = 0; i < 8; i++)
#pragma unroll
        for (int q = 0; q < 4; q++) acc2[i][q] = 0ull;

    for (int base = sb; base < se; base += 32) {
        int nv = se - base;
        if (nv > 32) nv = 32;
        __syncthreads();
        if (tid < 32)
            sidx[tid] = (tid < nv) ? d_idx[cstart + base + tid] : -1;
        __syncthreads();
        {
            int s = sidx[lt];
            if (s >= 0) {
                const float* xr = X + (size_t)s * p;
#pragma unroll
                for (int q = 0; q < 4; q++) {
                    int col = lc * 16 + q * 4;
                    *(float4*)&sA[lt][col] = *(const float4*)&xr[a0 + col];
                    *(float4*)&sB[lt][col] = *(const float4*)&xr[b0 + col];
                }
            }
        }
        __syncthreads();

        for (int t = 0; t < nv; t++) {
            float a[8];
            ull ad[8], b2[4];
            *(float4*)&a[0] = *(const float4*)&sA[t][ty * 8];
            *(float4*)&a[4] = *(const float4*)&sA[t][ty * 8 + 4];
#pragma unroll
            for (int i = 0; i < 8; i++) ad[i] = dup2(a[i]);
#pragma unroll
            for (int q = 0; q < 4; q++)
                b2[q] = *(const ull*)&sB[t][tx * 2 + q * 32];
#pragma unroll
            for (int i = 0; i < 8; i++)
#pragma unroll
                for (int q = 0; q < 4; q++)
                    acc2[i][q] = ffma2(ad[i], b2[q], acc2[i][q]);
        }
    }

    float* G = d_Gk[z][c];
    int gi = a0 + ty * 8;
#pragma unroll
    for (int i = 0; i < 8; i++)
#pragma unroll
        for (int q = 0; q < 4; q++) {
            float2 v = unpk2(acc2[i][q]);
            int col = b0 + q * 32 + tx * 2;
            *(float2*)&G[(size_t)(gi + i) * P + col] = v;
        }
    if (ti != tj) {
#pragma unroll
        for (int i = 0; i < 8; i++)
#pragma unroll
            for (int q = 0; q < 4; q++) {
                float2 v = unpk2(acc2[i][q]);
                int col = b0 + q * 32 + tx * 2;
                G[(size_t)col * P + gi + i]       = v.x;
                G[(size_t)(col + 1) * P + gi + i] = v.y;
            }
    }
}

// --------- assemble ---------------------------------------------------------
__global__ __launch_bounds__(256) void k_assemble(int m, float pf) {
    int idx4 = blockIdx.x * blockDim.x + threadIdx.x;
    if (idx4 >= P * P / 4) return;
    int idx = idx4 * 4;
    int r = idx >> 9, c0 = idx & 511;
    int kv = d_kval;
    float dg[4];
#pragma unroll
    for (int q = 0; q < 4; q++) dg[q] = (r == c0 + q) ? 1.f : 0.f;
    float sum[4] = {0.f, 0.f, 0.f, 0.f};
    for (int j = 0; j < kv; j++) {
        float4 g0 = *(const float4*)&d_Gk[0][j][idx];
        float4 g1 = *(const float4*)&d_Gk[1][j][idx];
        float4 g2 = *(const float4*)&d_Gk[2][j][idx];
        float g[4];
        g[0] = g0.x + g1.x + g2.x; g[1] = g0.y + g1.y + g2.y;
        g[2] = g0.z + g1.z + g2.z; g[3] = g0.w + g1.w + g2.w;
        float scal = pf / (((float)d_cnt[j] + 1e-8f) * 0.01f);
        float4 o;
        o.x = dg[0] + scal * g[0]; o.y = dg[1] + scal * g[1];
        o.z = dg[2] + scal * g[2]; o.w = dg[3] + scal * g[3];
        *(float4*)&d_A[j][idx] = o;
#pragma unroll
        for (int q = 0; q < 4; q++) sum[q] += g[q];
    }
    float scalar = pf / ((float)m * 0.01f);
    float4 o;
    o.x = dg[0] + scalar * sum[0]; o.y = dg[1] + scalar * sum[1];
    o.z = dg[2] + scalar * sum[2]; o.w = dg[3] + scalar * sum[3];
    *(float4*)&d_A[kv][idx] = o;
}

// ---- diag core: factor 64x64 in sD, logdet, Z=L^-1, Dinv -> parity buf ----
__device__ void diag_core(int mb, int s, int tid, float* sD, float* sZ,
                          float* sW, float* sdinv, float* sRed) {
    bool needZ = (s < NSTEP - 1);
    if (needZ)
        for (int l = tid; l < NB * 65; l += 256) sZ[l] = 0.f;
    __syncthreads();

#pragma unroll 1
    for (int b = 0; b < NB; b += 8) {
        if (tid < 32) {
#pragma unroll
            for (int t = 0; t < 8; t++) {
                int tt = b + t;
                if (tid == 0) {
                    float dv = sqrtf(sD[tt * 65 + tt]);
                    sD[tt * 65 + tt] = dv;
                    sdinv[tt] = 1.f / dv;
                }
                __syncwarp();
                float dinv = sdinv[tt];
                if (tid > t && tid < 8)
                    sD[(b + tid) * 65 + tt] *= dinv;
                __syncwarp();
                int i = tid >> 2, u = tid & 3;
#pragma unroll
                for (int pass = 0; pass < 2; pass++) {
                    int uu = u + pass * 4;
                    if (uu > t && i >= uu)
                        sD[(b + i) * 65 + b + uu] =
                            fmaf(-sD[(b + i) * 65 + tt],
                                 sD[(b + uu) * 65 + tt],
                                 sD[(b + i) * 65 + b + uu]);
                }
                __syncwarp();
            }
        }
        __syncthreads();

        int rows = NB - b - 8;
        if (rows > 0) {
            if (tid < rows) {
                int r = b + 8 + tid;
                float x[8];
#pragma unroll
                for (int t = 0; t < 8; t++) x[t] = sD[r * 65 + b + t];
#pragma unroll
                for (int t = 0; t < 8; t++) {
                    float v = x[t];
#pragma unroll
                    for (int u = 0; u < t; u++)
                        v = fmaf(-x[u], sD[(b + t) * 65 + b + u], v);
                    x[t] = v * sdinv[b + t];
                }
#pragma unroll
                for (int t = 0; t < 8; t++) sD[r * 65 + b + t] = x[t];
            }
            __syncthreads();

            for (int l = tid; l < rows * rows; l += 256) {
                int i = b + 8 + l / rows, u = b + 8 + l % rows;
                float acc = sD[i * 65 + u];
#pragma unroll
                for (int t = 0; t < 8; t++)
                    acc = fmaf(-sD[i * 65 + b + t], sD[u * 65 + b + t], acc);
                sD[i * 65 + u] = acc;
            }
        }
        __syncthreads();
    }

    if (tid < NB) sRed[tid] = logf(sD[tid * 65 + tid]);
    __syncthreads();
    if (tid == 0) {
        double acc = 0.0;
        for (int t = 0; t < NB; t++) acc += (double)sRed[t];
        d_hldd[mb] += acc;
    }
    if (!needZ) return;

    for (int b = 0; b < NB; b += 8) {
        {
            int t0 = tid >> 6;
            int j = tid & 63;
#pragma unroll
            for (int pass = 0; pass < 2; pass++) {
                int t = t0 + pass * 4;
                float acc = 0.f;
                for (int u = 0; u < b; u++)
                    acc = fmaf(sD[(b + t) * 65 + u], sZ[u * 65 + j], acc);
                sW[t * 64 + j] = acc;
            }
        }
        __syncthreads();
        if (tid < 64) {
            int j = tid;
#pragma unroll
            for (int t = 0; t < 8; t++) {
                int r = b + t;
                if (j <= r) {
                    float v = ((r == j) ? 1.f : 0.f) - sW[t * 64 + j];
#pragma unroll
                    for (int u = 0; u < 8; u++) {
                        if (u < t)
                            v = fmaf(-sD[r * 65 + b + u], sZ[(b + u) * 65 + j],
                                     v);
                    }
                    sZ[r * 65 + j] = v * sdinv[r];
                }
            }
        }
        __syncthreads();
    }

    float* DI = d_Dinv[s & 1][mb];
    for (int l = tid; l < NB * NB; l += 256) {
        int t = l >> 6, u = l & 63;
        int w0 = t > u ? t : u;
        float acc = 0.f;
        for (int w = w0; w < NB; w++)
            acc = fmaf(sZ[w * 65 + t], sZ[w * 65 + u], acc);
        DI[t * DP + u] = acc;
    }
}

// ---- one trailing tile: C_ij -= A_i * Dinv * A_j^T; optional fused diag ---
__device__ void do_step_tile(float* A, int s, int l, bool fused, int mb,
                             float* fs, int tid) {
    int sc = s * NB;
    int ti = 0;
    while ((ti + 1) * (ti + 2) / 2 <= l) ti++;
    int tj = l - ti * (ti + 1) / 2;
    int ri = sc + NB + ti * NB, rj = sc + NB + tj * NB;
    float* sDv  = fs;
    float* sAjT = fs + NB * DP;
    float* sAiT = fs + 2 * NB * DP;
    float* sT   = fs + 3 * NB * DP;

    __syncthreads();
    {
        int j = tid >> 2, u0 = (tid & 3) * 16;
        const float* rowj = &A[(size_t)(rj + j) * P + sc];
        const float* rowi = &A[(size_t)(ri + j) * P + sc];
#pragma unroll
        for (int q4 = 0; q4 < 4; q4++) {
            float4 vj = *(const float4*)&rowj[u0 + q4 * 4];
            float4 vi = *(const float4*)&rowi[u0 + q4 * 4];
            int u = u0 + q4 * 4;
            sAjT[(u + 0) * DP + j] = vj.x; sAjT[(u + 1) * DP + j] = vj.y;
            sAjT[(u + 2) * DP + j] = vj.z; sAjT[(u + 3) * DP + j] = vj.w;
            sAiT[(u + 0) * DP + j] = vi.x; sAiT[(u + 1) * DP + j] = vi.y;
            sAiT[(u + 2) * DP + j] = vi.z; sAiT[(u + 3) * DP + j] = vi.w;
        }
    }
    __syncthreads();

    int tx = tid & 15, ty = tid >> 4;

    // GEMM1: T[t][j] = sum_u Dinv[t][u] * A_j[j][u]
    {
        ull acc2[4][2];
#pragma unroll
        for (int i = 0; i < 4; i++) { acc2[i][0] = 0ull; acc2[i][1] = 0ull; }
#pragma unroll 8
        for (int u = 0; u < NB; u++) {
            float4 av = *(const float4*)&sDv[u * DP + ty * 4];
            float4 bv = *(const float4*)&sAjT[u * DP + tx * 4];
            ull b0 = pack2(bv.x, bv.y), b1 = pack2(bv.z, bv.w);
            ull a0 = dup2(av.x), a1 = dup2(av.y);
            ull a2 = dup2(av.z), a3 = dup2(av.w);
            acc2[0][0] = ffma2(a0, b0, acc2[0][0]);
            acc2[0][1] = ffma2(a0, b1, acc2[0][1]);
            acc2[1][0] = ffma2(a1, b0, acc2[1][0]);
            acc2[1][1] = ffma2(a1, b1, acc2[1][1]);
            acc2[2][0] = ffma2(a2, b0, acc2[2][0]);
            acc2[2][1] = ffma2(a2, b1, acc2[2][1]);
            acc2[3][0] = ffma2(a3, b0, acc2[3][0]);
            acc2[3][1] = ffma2(a3, b1, acc2[3][1]);
        }
#pragma unroll
        for (int i = 0; i < 4; i++) {
            float2 lo = unpk2(acc2[i][0]), hi = unpk2(acc2[i][1]);
            float4 v; v.x = lo.x; v.y = lo.y; v.z = hi.x; v.w = hi.y;
            *(float4*)&sT[(ty * 4 + i) * DP + tx * 4] = v;
        }
    }
    __syncthreads();

    // GEMM2
    ull acc2[4][2];
#pragma unroll
    for (int i = 0; i < 4; i++) { acc2[i][0] = 0ull; acc2[i][1] = 0ull; }
#pragma unroll 8
    for (int t = 0; t < NB; t++) {
        float4 av = *(const float4*)&sAiT[t * DP + ty * 4];
        float4 bv = *(const float4*)&sT[t * DP + tx * 4];
        ull b0 = pack2(bv.x, bv.y), b1 = pack2(bv.z, bv.w);
        ull a0 = dup2(av.x), a1 = dup2(av.y);
        ull a2 = dup2(av.z), a3 = dup2(av.w);
        acc2[0][0] = ffma2(a0, b0, acc2[0][0]);
        acc2[0][1] = ffma2(a0, b1, acc2[0][1]);
        acc2[1][0] = ffma2(a1, b0, acc2[1][0]);
        acc2[1][1] = ffma2(a1, b1, acc2[1][1]);
        acc2[2][0] = ffma2(a2, b0, acc2[2][0]);
        acc2[2][1] = ffma2(a2, b1, acc2[2][1]);
        acc2[3][0] = ffma2(a3, b0, acc2[3][0]);
        acc2[3][1] = ffma2(a3, b1, acc2[3][1]);
    }

    if (!fused) {
#pragma unroll
        for (int q = 0; q < 4; q++) {
            float2 lo = unpk2(acc2[q][0]), hi = unpk2(acc2[q][1]);
            float* row = &A[(size_t)(ri + ty * 4 + q) * P + rj + tx * 4];
            float4 v = *(float4*)row;
            v.x -= lo.x; v.y -= lo.y; v.z -= hi.x; v.w -= hi.y;
            *(float4*)row = v;
        }
        return;
    }

    // fused tile(0,0): build next diag block in smem and factor it
    float* sD    = fs;
    float* sdinv = fs + 4160;
    float* sRed  = fs + 4224;
    float* sW    = fs + 4288;
    float* sZ    = fs + 2 * NB * DP;

#pragma unroll
    for (int q = 0; q < 4; q++) {
        float2 lo = unpk2(acc2[q][0]), hi = unpk2(acc2[q][1]);
        const float* row = &A[(size_t)(ri + ty * 4 + q) * P + rj + tx * 4];
        float4 v = *(const float4*)row;
        int rr = ty * 4 + q, cc = tx * 4;
        sD[rr * 65 + cc + 0] = v.x - lo.x;
        sD[rr * 65 + cc + 1] = v.y - lo.y;
        sD[rr * 65 + cc + 2] = v.z - hi.x;
        sD[rr * 65 + cc + 3] = v.w - hi.y;
    }
    __syncthreads();

    diag_core(mb, s + 1, tid, sD, sZ, sW, sdinv, sRed);
}

// ---- k_chol: persistent — all 8 steps + final scalars in ONE launch -------
__global__ __launch_bounds__(256) void k_chol(float* out, int m) {
    int cx = blockIdx.x;
    int mb = blockIdx.y;
    if (mb > d_kval) return;
    extern __shared__ float fs[];
    int tid = threadIdx.x;
    float* A = d_A[mb];

    float* sD    = fs;
    float* sdinv = fs + 4160;
    float* sRed  = fs + 4224;
    float* sW    = fs + 4288;
    float* sZ    = fs + 2 * NB * DP;

    if (cx == 0) {
        for (int l = tid; l < NB * NB; l += 256) {
            int r = l >> 6, c = l & 63;
            sD[r * 65 + c] = A[(size_t)r * P + c];
        }
        diag_core(mb, 0, tid, sD, sZ, sW, sdinv, sRed);
    }
    int ep = 1;
    mbar(mb, NCTA * ep);

    for (int s = 0; s < NSTEP - 1; s++) {
        int nblk = NSTEP - 1 - s;
        int ntile = nblk * (nblk + 1) / 2;

        // load this step's Dinv once (sDv = fs[0..NB*DP))
        {
            const float* DI = d_Dinv[s & 1][mb];
            for (int q = tid; q < NB * DP / 4; q += 256)
                *(float4*)&fs[q * 4] = *(const float4*)&DI[q * 4];
        }

        if (cx == 0) {
            do_step_tile(A, s, 0, true, mb, fs, tid);
        } else {
            for (int l = cx; l < ntile; l += NCTA - 1)
                do_step_tile(A, s, l, false, mb, fs, tid);
        }
        ep++;
        mbar(mb, NCTA * ep);
    }

    // finalize: per-matrix CTA0 signals; matrix 0 reduces and writes output
    if (cx == 0 && tid == 0) {
        __threadfence();
        atomicAdd(&d_done, 1);
        if (mb == 0) {
            int kv = d_kval;
            while (atomicAdd(&d_done, 0) < kv + 1) __nanosleep(64);
            __threadfence();
            double comp = 0.0;
            for (int j = 0; j < kv; j++) {
                double trPi = (double)d_cnt[j] + 1e-8;
                comp += d_hldd[j] * trPi / (double)m;
            }
            out[0] = (float)d_hldd[kv];
            out[1] = (float)comp;
            d_lbar = 0;   // reset labels barrier for next graph replay
        }
    }
}

// ---------------- launch ----------------------------------------------------
extern "C" void kernel_launch(void* const* d_in, const int* in_sizes, int n_in,
                              void* d_out, int out_size) {
    const float* X    = (const float*)d_in[0];
    const void*  Y    = d_in[1];
    const int*   ncls = (n_in >= 3) ? (const int*)d_in[2] : nullptr;
    int m = in_sizes[1];
    int p = in_sizes[0] / m;          // 512
    float* out = (float*)d_out;
    (void)out_size;
    int nchunk = (m + 255) / 256;

    cudaFuncSetAttribute(k_chol, cudaFuncAttributeMaxDynamicSharedMemorySize,
                         FT_SMEM_BYTES);

    k_labels<<<nchunk, 256>>>(Y, ncls, m, nchunk);
    k_gram<<<dim3(10, K_MAX, NSLICE), 256>>>(X, p);
    k_assemble<<<(P * P / 4 + 255) / 256, 256>>>(m, (float)p);
    k_chol<<<dim3(NCTA, NM), 256, FT_SMEM_BYTES>>>(out, m);
}

// round 10
// speedup vs baseline: 1.2584x; 1.2584x over previous
#include <cuda_runtime.h>
#include <math.h>

#define P       512
#define K_MAX   16
#define NM      (K_MAX + 1)
#define M_CAP   65536
#define NCH_MAX 256
#define NB      64
#define NSTEP   (P / NB)      // 8
#define NSLICE  3
#define DP      68
#define NCTA    15            // CTAs per matrix in persistent chol

#define FT_SMEM_BYTES (4 * NB * DP * 4)   // 69632 B

typedef unsigned long long ull;

// ---------------- f32x2 packed helpers (Blackwell sm_103a) -----------------
__device__ __forceinline__ ull ffma2(ull a, ull b, ull c) {
    ull d;
    asm("fma.rn.f32x2 %0, %1, %2, %3;" : "=l"(d) : "l"(a), "l"(b), "l"(c));
    return d;
}
__device__ __forceinline__ ull dup2(float x) {
    ull r; unsigned xb = __float_as_uint(x);
    asm("mov.b64 %0, {%1, %2};" : "=l"(r) : "r"(xb), "r"(xb));
    return r;
}
__device__ __forceinline__ ull pack2(float lo, float hi) {
    ull r;
    asm("mov.b64 %0, {%1, %2};" : "=l"(r) : "f"(lo), "f"(hi));
    return r;
}
__device__ __forceinline__ float2 unpk2(ull v) {
    float2 r;
    asm("mov.b64 {%0, %1}, %2;" : "=f"(r.x), "=f"(r.y) : "l"(v));
    return r;
}

// ---------------- device scratch -------------------------------------------
__device__ int    d_cnt[K_MAX];
__device__ int    d_kval;
__device__ int    d_idx[M_CAP];
__device__ int    d_bh[NCH_MAX][K_MAX];
__device__ int    d_boff[NCH_MAX][K_MAX];
__device__ int    d_cstart[K_MAX];
__device__ int    d_lbar;
__device__ int    d_bar[NM];
__device__ int    d_done;
__device__ float  d_Gk[NSLICE][K_MAX][P * P];
__device__ float  d_A[NM][P * P];
__device__ float  d_Dinv[2][NM][NB * DP];
__device__ double d_hldd[NM];

// ---------------- global barrier for k_labels (hard spin) ------------------
__device__ __forceinline__ void gbar(int nb, int ep) {
    __syncthreads();
    __threadfence();
    if (threadIdx.x == 0) {
        atomicAdd(&d_lbar, 1);
        volatile int* p = &d_lbar;
        while (*p < nb * ep) { }
        __threadfence();
    }
    __syncthreads();
}

// ---------------- per-matrix barrier for k_chol (hard spin) ----------------
__device__ __forceinline__ void mbar(int mb, int target) {
    __syncthreads();
    __threadfence();
    if (threadIdx.x == 0) {
        atomicAdd(&d_bar[mb], 1);
        volatile int* p = &d_bar[mb];
        while (*p < target) { }
        __threadfence();
    }
    __syncthreads();
}

// ------- k_labels: dtype detect + hist + scan + stable scatter (1 launch) --
__global__ __launch_bounds__(256) void k_labels(const void* __restrict__ Y,
                                                const int* ncls, int m,
                                                int nchunk) {
    __shared__ int sh[K_MAX];
    __shared__ int swh[8 * K_MAX];
    __shared__ int nzf;
    int tid = threadIdx.x;
    int b = blockIdx.x;
    if (tid == 0) nzf = 0;
    if (tid < K_MAX) sh[tid] = 0;
    __syncthreads();

    int lim = m / 2; if (lim > 512) lim = 512;
    int found = 0;
    for (int i = tid; i < lim; i += 256)
        if (((const int*)Y)[2 * i + 1] != 0) found = 1;
    if (__any_sync(0xffffffffu, found)) {
        if ((tid & 31) == 0) atomicOr(&nzf, 1);
    }
    __syncthreads();
    int is64 = nzf ? 0 : 1;

    int i = b * 256 + tid;
    int c = -1;
    if (i < m) {
        c = is64 ? (int)((const long long*)Y)[i] : ((const int*)Y)[i];
        if (c < 0 || c >= K_MAX) c = 0;
        atomicAdd(&sh[c], 1);
    }
    __syncthreads();
    if (tid < K_MAX) d_bh[b][tid] = sh[tid];

    gbar(nchunk, 1);

    if (b == 0) {
        if (tid < K_MAX) {
            int run = 0;
            for (int bb = 0; bb < nchunk; bb++) {
                d_boff[bb][tid] = run;
                run += d_bh[bb][tid];
            }
            d_cnt[tid] = run;
            sh[tid] = run;
        }
        __syncthreads();
        if (tid == 0) {
            int run = 0;
            for (int cc = 0; cc < K_MAX; cc++) {
                d_cstart[cc] = run;
                run += sh[cc];
            }
            int k = ncls ? *ncls : 10;
            if (k < 1) k = 1;
            if (k > K_MAX) k = K_MAX;
            d_kval = k;
            d_done = 0;
        }
        if (tid < NM) { d_hldd[tid] = 0.0; d_bar[tid] = 0; }
    }

    gbar(nchunk, 2);

    if (tid < 8 * K_MAX) swh[tid] = 0;
    __syncthreads();
    int lane = tid & 31, w = tid >> 5;
    unsigned mask = __match_any_sync(0xffffffffu, c);
    int rin = __popc(mask & ((1u << lane) - 1u));
    int leader = __ffs(mask) - 1;
    if (c >= 0 && lane == leader) swh[w * K_MAX + c] = __popc(mask);
    __syncthreads();
    if (c >= 0) {
        int pre = 0;
        for (int w2 = 0; w2 < w; w2++) pre += swh[w2 * K_MAX + c];
        d_idx[d_cstart[c] + d_boff[b][c] + pre + rin] = i;
    }
}

// ------- per-class Gram: dense gather over sorted class range --------------
__global__ __launch_bounds__(256) void k_gram(const float* __restrict__ X,
                                              int p) {
    int c = blockIdx.y;
    if (c >= d_kval) return;
    int tile = blockIdx.x;
    int ti = 0;
    while ((ti + 1) * (ti + 2) / 2 <= tile) ti++;
    int tj = tile - ti * (ti + 1) / 2;
    int a0 = ti * 128, b0 = tj * 128;
    int z = blockIdx.z;
    int cstart = d_cstart[c], ccnt = d_cnt[c];
    int sb = (int)((long long)ccnt * z / NSLICE);
    int se = (int)((long long)ccnt * (z + 1) / NSLICE);

    __shared__ __align__(16) float sA[32][132];
    __shared__ __align__(16) float sB[32][132];
    __shared__ int sidx[32];

    int tid = threadIdx.x;
    int tx = tid & 15, ty = tid >> 4;
    int lt = tid >> 3, lc = tid & 7;

    ull acc2[8][4];
#pragma unroll
    for (int i = 0; i < 8; i++)
#pragma unroll
        for (int q = 0; q < 4; q++) acc2[i][q] = 0ull;

    for (int base = sb; base < se; base += 32) {
        int nv = se - base;
        if (nv > 32) nv = 32;
        __syncthreads();
        if (tid < 32)
            sidx[tid] = (tid < nv) ? d_idx[cstart + base + tid] : -1;
        __syncthreads();
        {
            int s = sidx[lt];
            if (s >= 0) {
                const float* xr = X + (size_t)s * p;
#pragma unroll
                for (int q = 0; q < 4; q++) {
                    int col = lc * 16 + q * 4;
                    *(float4*)&sA[lt][col] = *(const float4*)&xr[a0 + col];
                    *(float4*)&sB[lt][col] = *(const float4*)&xr[b0 + col];
                }
            }
        }
        __syncthreads();

        for (int t = 0; t < nv; t++) {
            float a[8];
            ull ad[8], b2[4];
            *(float4*)&a[0] = *(const float4*)&sA[t][ty * 8];
            *(float4*)&a[4] = *(const float4*)&sA[t][ty * 8 + 4];
#pragma unroll
            for (int i = 0; i < 8; i++) ad[i] = dup2(a[i]);
#pragma unroll
            for (int q = 0; q < 4; q++)
                b2[q] = *(const ull*)&sB[t][tx * 2 + q * 32];
#pragma unroll
            for (int i = 0; i < 8; i++)
#pragma unroll
                for (int q = 0; q < 4; q++)
                    acc2[i][q] = ffma2(ad[i], b2[q], acc2[i][q]);
        }
    }

    float* G = d_Gk[z][c];
    int gi = a0 + ty * 8;
#pragma unroll
    for (int i = 0; i < 8; i++)
#pragma unroll
        for (int q = 0; q < 4; q++) {
            float2 v = unpk2(acc2[i][q]);
            int col = b0 + q * 32 + tx * 2;
            *(float2*)&G[(size_t)(gi + i) * P + col] = v;
        }
    if (ti != tj) {
#pragma unroll
        for (int i = 0; i < 8; i++)
#pragma unroll
            for (int q = 0; q < 4; q++) {
                float2 v = unpk2(acc2[i][q]);
                int col = b0 + q * 32 + tx * 2;
                G[(size_t)col * P + gi + i]       = v.x;
                G[(size_t)(col + 1) * P + gi + i] = v.y;
            }
    }
}

// --------- assemble ---------------------------------------------------------
__global__ __launch_bounds__(256) void k_assemble(int m, float pf) {
    int idx4 = blockIdx.x * blockDim.x + threadIdx.x;
    if (idx4 >= P * P / 4) return;
    int idx = idx4 * 4;
    int r = idx >> 9, c0 = idx & 511;
    int kv = d_kval;
    float dg[4];
#pragma unroll
    for (int q = 0; q < 4; q++) dg[q] = (r == c0 + q) ? 1.f : 0.f;
    float sum[4] = {0.f, 0.f, 0.f, 0.f};
    for (int j = 0; j < kv; j++) {
        float4 g0 = *(const float4*)&d_Gk[0][j][idx];
        float4 g1 = *(const float4*)&d_Gk[1][j][idx];
        float4 g2 = *(const float4*)&d_Gk[2][j][idx];
        float g[4];
        g[0] = g0.x + g1.x + g2.x; g[1] = g0.y + g1.y + g2.y;
        g[2] = g0.z + g1.z + g2.z; g[3] = g0.w + g1.w + g2.w;
        float scal = pf / (((float)d_cnt[j] + 1e-8f) * 0.01f);
        float4 o;
        o.x = dg[0] + scal * g[0]; o.y = dg[1] + scal * g[1];
        o.z = dg[2] + scal * g[2]; o.w = dg[3] + scal * g[3];
        *(float4*)&d_A[j][idx] = o;
#pragma unroll
        for (int q = 0; q < 4; q++) sum[q] += g[q];
    }
    float scalar = pf / ((float)m * 0.01f);
    float4 o;
    o.x = dg[0] + scalar * sum[0]; o.y = dg[1] + scalar * sum[1];
    o.z = dg[2] + scalar * sum[2]; o.w = dg[3] + scalar * sum[3];
    *(float4*)&d_A[kv][idx] = o;
}

// ---- diag core: factor 64x64 in sD, logdet, Z=L^-1, Dinv ------------------
// Dinv goes to global parity buffer AND to sDvOut (CTA0's own smem, fs base).
__device__ void diag_core(int mb, int s, int tid, float* sD, float* sZ,
                          float* sW, float* sdinv, float* sRed,
                          float* sDvOut) {
    bool needZ = (s < NSTEP - 1);
    if (needZ)
        for (int l = tid; l < NB * 65; l += 256) sZ[l] = 0.f;
    __syncthreads();

#pragma unroll 1
    for (int b = 0; b < NB; b += 8) {
        // ---- 8x8 diag sub-factor: one thread, registers, rsqrt ----
        if (tid == 0) {
            float a[8][8];
#pragma unroll
            for (int i = 0; i < 8; i++)
#pragma unroll
                for (int u = 0; u <= i; u++)
                    a[i][u] = sD[(b + i) * 65 + b + u];
#pragma unroll
            for (int t = 0; t < 8; t++) {
                float rinv = rsqrtf(a[t][t]);
                a[t][t] *= rinv;          // = sqrt
                sdinv[b + t] = rinv;
#pragma unroll
                for (int i = t + 1; i < 8; i++) a[i][t] *= rinv;
#pragma unroll
                for (int u = t + 1; u < 8; u++)
#pragma unroll
                    for (int i = u; i < 8; i++)
                        a[i][u] = fmaf(-a[i][t], a[u][t], a[i][u]);
            }
#pragma unroll
            for (int i = 0; i < 8; i++)
#pragma unroll
                for (int u = 0; u <= i; u++)
                    sD[(b + i) * 65 + b + u] = a[i][u];
        }
        __syncthreads();

        int rows = NB - b - 8;
        if (rows > 0) {
            if (tid < rows) {
                int r = b + 8 + tid;
                float x[8];
#pragma unroll
                for (int t = 0; t < 8; t++) x[t] = sD[r * 65 + b + t];
#pragma unroll
                for (int t = 0; t < 8; t++) {
                    float v = x[t];
#pragma unroll
                    for (int u = 0; u < t; u++)
                        v = fmaf(-x[u], sD[(b + t) * 65 + b + u], v);
                    x[t] = v * sdinv[b + t];
                }
#pragma unroll
                for (int t = 0; t < 8; t++) sD[r * 65 + b + t] = x[t];
            }
            __syncthreads();

            // rank-8 update, no integer division
            int total = rows << 6;
            for (int l = tid; l < total; l += 256) {
                int i = b + 8 + (l >> 6), u = l & 63;
                if (u >= b + 8) {
                    float acc = sD[i * 65 + u];
#pragma unroll
                    for (int t = 0; t < 8; t++)
                        acc = fmaf(-sD[i * 65 + b + t], sD[u * 65 + b + t],
                                   acc);
                    sD[i * 65 + u] = acc;
                }
            }
        }
        __syncthreads();
    }

    if (tid < NB) sRed[tid] = logf(sD[tid * 65 + tid]);
    __syncthreads();
    if (tid < 32) {
        double lsum = (double)sRed[tid] + (double)sRed[tid + 32];
#pragma unroll
        for (int o = 16; o > 0; o >>= 1)
            lsum += __shfl_down_sync(0xffffffffu, lsum, o);
        if (tid == 0) d_hldd[mb] += lsum;
    }
    if (!needZ) return;

    // Z = L^{-1}: rank-8 panels
    for (int b = 0; b < NB; b += 8) {
        {
            int t0 = tid >> 6;
            int j = tid & 63;
#pragma unroll
            for (int pass = 0; pass < 2; pass++) {
                int t = t0 + pass * 4;
                float acc = 0.f;
                for (int u = 0; u < b; u++)
                    acc = fmaf(sD[(b + t) * 65 + u], sZ[u * 65 + j], acc);
                sW[t * 64 + j] = acc;
            }
        }
        __syncthreads();
        if (tid < 64) {
            int j = tid;
#pragma unroll
            for (int t = 0; t < 8; t++) {
                int r = b + t;
                if (j <= r) {
                    float v = ((r == j) ? 1.f : 0.f) - sW[t * 64 + j];
#pragma unroll
                    for (int u = 0; u < 8; u++) {
                        if (u < t)
                            v = fmaf(-sD[r * 65 + b + u], sZ[(b + u) * 65 + j],
                                     v);
                    }
                    sZ[r * 65 + j] = v * sdinv[r];
                }
            }
        }
        __syncthreads();
    }

    // Dinv = Z^T Z (symmetric half + mirror) -> global parity buf + own smem.
    // NOTE: writes [0, NB*DP) of fs — sD/sdinv/sRed/sW are dead by now.
    float* DI = d_Dinv[s & 1][mb];
    for (int l = tid; l < NB * NB; l += 256) {
        int t = l >> 6, u = l & 63;
        if (u < t) continue;
        float acc = 0.f;
        for (int w = u; w < NB; w++)
            acc = fmaf(sZ[w * 65 + t], sZ[w * 65 + u], acc);
        DI[t * DP + u] = acc;
        DI[u * DP + t] = acc;
        sDvOut[t * DP + u] = acc;
        sDvOut[u * DP + t] = acc;
    }
    __syncthreads();
}

// ---- one trailing tile: C_ij -= A_i * Dinv * A_j^T; optional fused diag ---
__device__ void do_step_tile(float* A, int s, int l, bool fused, int mb,
                             float* fs, int tid) {
    int sc = s * NB;
    int ti = 0;
    while ((ti + 1) * (ti + 2) / 2 <= l) ti++;
    int tj = l - ti * (ti + 1) / 2;
    int ri = sc + NB + ti * NB, rj = sc + NB + tj * NB;
    float* sDv  = fs;
    float* sAjT = fs + NB * DP;
    float* sAiT = fs + 2 * NB * DP;
    float* sT   = fs + 3 * NB * DP;

    __syncthreads();
    {
        int j = tid >> 2, u0 = (tid & 3) * 16;
        const float* rowj = &A[(size_t)(rj + j) * P + sc];
        const float* rowi = &A[(size_t)(ri + j) * P + sc];
#pragma unroll
        for (int q4 = 0; q4 < 4; q4++) {
            float4 vj = *(const float4*)&rowj[u0 + q4 * 4];
            float4 vi = *(const float4*)&rowi[u0 + q4 * 4];
            int u = u0 + q4 * 4;
            sAjT[(u + 0) * DP + j] = vj.x; sAjT[(u + 1) * DP + j] = vj.y;
            sAjT[(u + 2) * DP + j] = vj.z; sAjT[(u + 3) * DP + j] = vj.w;
            sAiT[(u + 0) * DP + j] = vi.x; sAiT[(u + 1) * DP + j] = vi.y;
            sAiT[(u + 2) * DP + j] = vi.z; sAiT[(u + 3) * DP + j] = vi.w;
        }
    }
    __syncthreads();

    int tx = tid & 15, ty = tid >> 4;

    // GEMM1: T[t][j] = sum_u Dinv[t][u] * A_j[j][u]
    {
        ull acc2[4][2];
#pragma unroll
        for (int i = 0; i < 4; i++) { acc2[i][0] = 0ull; acc2[i][1] = 0ull; }
#pragma unroll 8
        for (int u = 0; u < NB; u++) {
            float4 av = *(const float4*)&sDv[u * DP + ty * 4];
            float4 bv = *(const float4*)&sAjT[u * DP + tx * 4];
            ull b0 = pack2(bv.x, bv.y), b1 = pack2(bv.z, bv.w);
            ull a0 = dup2(av.x), a1 = dup2(av.y);
            ull a2 = dup2(av.z), a3 = dup2(av.w);
            acc2[0][0] = ffma2(a0, b0, acc2[0][0]);
            acc2[0][1] = ffma2(a0, b1, acc2[0][1]);
            acc2[1][0] = ffma2(a1, b0, acc2[1][0]);
            acc2[1][1] = ffma2(a1, b1, acc2[1][1]);
            acc2[2][0] = ffma2(a2, b0, acc2[2][0]);
            acc2[2][1] = ffma2(a2, b1, acc2[2][1]);
            acc2[3][0] = ffma2(a3, b0, acc2[3][0]);
            acc2[3][1] = ffma2(a3, b1, acc2[3][1]);
        }
#pragma unroll
        for (int i = 0; i < 4; i++) {
            float2 lo = unpk2(acc2[i][0]), hi = unpk2(acc2[i][1]);
            float4 v; v.x = lo.x; v.y = lo.y; v.z = hi.x; v.w = hi.y;
            *(float4*)&sT[(ty * 4 + i) * DP + tx * 4] = v;
        }
    }
    __syncthreads();

    // GEMM2
    ull acc2[4][2];
#pragma unroll
    for (int i = 0; i < 4; i++) { acc2[i][0] = 0ull; acc2[i][1] = 0ull; }
#pragma unroll 8
    for (int t = 0; t < NB; t++) {
        float4 av = *(const float4*)&sAiT[t * DP + ty * 4];
        float4 bv = *(const float4*)&sT[t * DP + tx * 4];
        ull b0 = pack2(bv.x, bv.y), b1 = pack2(bv.z, bv.w);
        ull a0 = dup2(av.x), a1 = dup2(av.y);
        ull a2 = dup2(av.z), a3 = dup2(av.w);
        acc2[0][0] = ffma2(a0, b0, acc2[0][0]);
        acc2[0][1] = ffma2(a0, b1, acc2[0][1]);
        acc2[1][0] = ffma2(a1, b0, acc2[1][0]);
        acc2[1][1] = ffma2(a1, b1, acc2[1][1]);
        acc2[2][0] = ffma2(a2, b0, acc2[2][0]);
        acc2[2][1] = ffma2(a2, b1, acc2[2][1]);
        acc2[3][0] = ffma2(a3, b0, acc2[3][0]);
        acc2[3][1] = ffma2(a3, b1, acc2[3][1]);
    }

    if (!fused) {
#pragma unroll
        for (int q = 0; q < 4; q++) {
            float2 lo = unpk2(acc2[q][0]), hi = unpk2(acc2[q][1]);
            float* row = &A[(size_t)(ri + ty * 4 + q) * P + rj + tx * 4];
            float4 v = *(float4*)row;
            v.x -= lo.x; v.y -= lo.y; v.z -= hi.x; v.w -= hi.y;
            *(float4*)row = v;
        }
        return;
    }

    // fused tile(0,0): build next diag block in smem and factor it
    float* sD    = fs;
    float* sdinv = fs + 4160;
    float* sRed  = fs + 4224;
    float* sW    = fs + 4288;
    float* sZ    = fs + 2 * NB * DP;

#pragma unroll
    for (int q = 0; q < 4; q++) {
        float2 lo = unpk2(acc2[q][0]), hi = unpk2(acc2[q][1]);
        const float* row = &A[(size_t)(ri + ty * 4 + q) * P + rj + tx * 4];
        float4 v = *(const float4*)row;
        int rr = ty * 4 + q, cc = tx * 4;
        sD[rr * 65 + cc + 0] = v.x - lo.x;
        sD[rr * 65 + cc + 1] = v.y - lo.y;
        sD[rr * 65 + cc + 2] = v.z - hi.x;
        sD[rr * 65 + cc + 3] = v.w - hi.y;
    }
    __syncthreads();

    diag_core(mb, s + 1, tid, sD, sZ, sW, sdinv, sRed, fs);
}

// ---- k_chol: persistent — all 8 steps + final scalars in ONE launch -------
__global__ __launch_bounds__(256) void k_chol(float* out, int m) {
    int cx = blockIdx.x;
    int mb = blockIdx.y;
    if (mb > d_kval) return;
    extern __shared__ float fs[];
    int tid = threadIdx.x;
    float* A = d_A[mb];

    float* sD    = fs;
    float* sdinv = fs + 4160;
    float* sRed  = fs + 4224;
    float* sW    = fs + 4288;
    float* sZ    = fs + 2 * NB * DP;

    if (cx == 0) {
        for (int l = tid; l < NB * NB; l += 256) {
            int r = l >> 6, c = l & 63;
            sD[r * 65 + c] = A[(size_t)r * P + c];
        }
        __syncthreads();
        diag_core(mb, 0, tid, sD, sZ, sW, sdinv, sRed, fs);
    }
    int ep = 1;
    mbar(mb, NCTA * ep);

    for (int s = 0; s < NSTEP - 1; s++) {
        int nblk = NSTEP - 1 - s;
        int ntile = nblk * (nblk + 1) / 2;

        if (cx == 0) {
            // Dinv already resident in fs[0..NB*DP) from previous diag_core
            do_step_tile(A, s, 0, true, mb, fs, tid);
        } else if (cx < ntile) {
            const float* DI = d_Dinv[s & 1][mb];
            for (int q = tid; q < NB * DP / 4; q += 256)
                *(float4*)&fs[q * 4] = *(const float4*)&DI[q * 4];
            for (int l = cx; l < ntile; l += NCTA - 1)
                do_step_tile(A, s, l, false, mb, fs, tid);
        }
        ep++;
        mbar(mb, NCTA * ep);
    }

    if (cx == 0 && tid == 0) {
        __threadfence();
        atomicAdd(&d_done, 1);
        if (mb == 0) {
            int kv = d_kval;
            volatile int* p = &d_done;
            while (*p < kv + 1) { }
            __threadfence();
            double comp = 0.0;
            for (int j = 0; j < kv; j++) {
                double trPi = (double)d_cnt[j] + 1e-8;
                comp += d_hldd[j] * trPi / (double)m;
            }
            out[0] = (float)d_hldd[kv];
            out[1] = (float)comp;
            d_lbar = 0;   // reset labels barrier for next graph replay
        }
    }
}

// ---------------- launch ----------------------------------------------------
extern "C" void kernel_launch(void* const* d_in, const int* in_sizes, int n_in,
                              void* d_out, int out_size) {
    const float* X    = (const float*)d_in[0];
    const void*  Y    = d_in[1];
    const int*   ncls = (n_in >= 3) ? (const int*)d_in[2] : nullptr;
    int m = in_sizes[1];
    int p = in_sizes[0] / m;          // 512
    float* out = (float*)d_out;
    (void)out_size;
    int nchunk = (m + 255) / 256;

    cudaFuncSetAttribute(k_chol, cudaFuncAttributeMaxDynamicSharedMemorySize,
                         FT_SMEM_BYTES);

    k_labels<<<nchunk, 256>>>(Y, ncls, m, nchunk);
    k_gram<<<dim3(10, K_MAX, NSLICE), 256>>>(X, p);
    k_assemble<<<(P * P / 4 + 255) / 256, 256>>>(m, (float)p);
    k_chol<<<dim3(NCTA, NM), 256, FT_SMEM_BYTES>>>(out, m);
}

// round 11
// speedup vs baseline: 1.4271x; 1.1341x over previous
#include <cuda_runtime.h>
#include <math.h>

#define P       512
#define K_MAX   16
#define NM      (K_MAX + 1)
#define M_CAP   65536
#define NCH_MAX 256
#define NB      64
#define NSTEP   (P / NB)      // 8
#define NSLICE  3
#define DP      68
#define NCTA    15            // CTAs per matrix in persistent chol

#define FT_SMEM_BYTES (17408 * 4)   // 69632 B

typedef unsigned long long ull;

// ---------------- f32x2 packed helpers (Blackwell sm_103a) -----------------
__device__ __forceinline__ ull ffma2(ull a, ull b, ull c) {
    ull d;
    asm("fma.rn.f32x2 %0, %1, %2, %3;" : "=l"(d) : "l"(a), "l"(b), "l"(c));
    return d;
}
__device__ __forceinline__ ull dup2(float x) {
    ull r; unsigned xb = __float_as_uint(x);
    asm("mov.b64 %0, {%1, %2};" : "=l"(r) : "r"(xb), "r"(xb));
    return r;
}
__device__ __forceinline__ ull pack2(float lo, float hi) {
    ull r;
    asm("mov.b64 %0, {%1, %2};" : "=l"(r) : "f"(lo), "f"(hi));
    return r;
}
__device__ __forceinline__ float2 unpk2(ull v) {
    float2 r;
    asm("mov.b64 {%0, %1}, %2;" : "=f"(r.x), "=f"(r.y) : "l"(v));
    return r;
}

// ---------------- device scratch -------------------------------------------
__device__ int    d_cnt[K_MAX];
__device__ int    d_kval;
__device__ int    d_idx[M_CAP];
__device__ int    d_bh[NCH_MAX][K_MAX];
__device__ int    d_boff[NCH_MAX][K_MAX];
__device__ int    d_cstart[K_MAX];
__device__ int    d_lbar;
__device__ int    d_bar[NM];
__device__ int    d_done;
__device__ float  d_Gk[NSLICE][K_MAX][P * P];
__device__ float  d_A[NM][P * P];
__device__ float  d_Z[NM][NB * 65];
__device__ float  d_W[NM][NSTEP - 1][NB * DP];
__device__ double d_hldd[NM];

// ---------------- release/acquire spin barriers ----------------------------
__device__ __forceinline__ void rel_add(int* p) {
    int d;
    asm volatile("atom.release.gpu.add.s32 %0, [%1], 1;"
                 : "=r"(d) : "l"(p) : "memory");
}
__device__ __forceinline__ int acq_ld(const int* p) {
    int v;
    asm volatile("ld.acquire.gpu.s32 %0, [%1];" : "=r"(v) : "l"(p) : "memory");
    return v;
}
__device__ __forceinline__ void gbar(int nb, int ep) {
    __syncthreads();
    if (threadIdx.x == 0) {
        rel_add(&d_lbar);
        while (acq_ld(&d_lbar) < nb * ep) { }
    }
    __syncthreads();
}
__device__ __forceinline__ void mbar(int mb, int target) {
    __syncthreads();
    if (threadIdx.x == 0) {
        rel_add(&d_bar[mb]);
        while (acq_ld(&d_bar[mb]) < target) { }
    }
    __syncthreads();
}

// ------- k_labels: dtype detect + hist + scan + stable scatter (1 launch) --
__global__ __launch_bounds__(256) void k_labels(const void* __restrict__ Y,
                                                const int* ncls, int m,
                                                int nchunk) {
    __shared__ int sh[K_MAX];
    __shared__ int swh[8 * K_MAX];
    __shared__ int nzf;
    int tid = threadIdx.x;
    int b = blockIdx.x;
    if (tid == 0) nzf = 0;
    if (tid < K_MAX) sh[tid] = 0;
    __syncthreads();

    int lim = m / 2; if (lim > 512) lim = 512;
    int found = 0;
    for (int i = tid; i < lim; i += 256)
        if (((const int*)Y)[2 * i + 1] != 0) found = 1;
    if (__any_sync(0xffffffffu, found)) {
        if ((tid & 31) == 0) atomicOr(&nzf, 1);
    }
    __syncthreads();
    int is64 = nzf ? 0 : 1;

    int i = b * 256 + tid;
    int c = -1;
    if (i < m) {
        c = is64 ? (int)((const long long*)Y)[i] : ((const int*)Y)[i];
        if (c < 0 || c >= K_MAX) c = 0;
        atomicAdd(&sh[c], 1);
    }
    __syncthreads();
    if (tid < K_MAX) d_bh[b][tid] = sh[tid];

    gbar(nchunk, 1);

    if (b == 0) {
        if (tid < K_MAX) {
            int run = 0;
            for (int bb = 0; bb < nchunk; bb++) {
                d_boff[bb][tid] = run;
                run += d_bh[bb][tid];
            }
            d_cnt[tid] = run;
            sh[tid] = run;
        }
        __syncthreads();
        if (tid == 0) {
            int run = 0;
            for (int cc = 0; cc < K_MAX; cc++) {
                d_cstart[cc] = run;
                run += sh[cc];
            }
            int k = ncls ? *ncls : 10;
            if (k < 1) k = 1;
            if (k > K_MAX) k = K_MAX;
            d_kval = k;
            d_done = 0;
        }
        if (tid < NM) { d_hldd[tid] = 0.0; d_bar[tid] = 0; }
    }

    gbar(nchunk, 2);

    if (tid < 8 * K_MAX) swh[tid] = 0;
    __syncthreads();
    int lane = tid & 31, w = tid >> 5;
    unsigned mask = __match_any_sync(0xffffffffu, c);
    int rin = __popc(mask & ((1u << lane) - 1u));
    int leader = __ffs(mask) - 1;
    if (c >= 0 && lane == leader) swh[w * K_MAX + c] = __popc(mask);
    __syncthreads();
    if (c >= 0) {
        int pre = 0;
        for (int w2 = 0; w2 < w; w2++) pre += swh[w2 * K_MAX + c];
        d_idx[d_cstart[c] + d_boff[b][c] + pre + rin] = i;
    }
}

// ------- per-class Gram: dense gather over sorted class range --------------
__global__ __launch_bounds__(256) void k_gram(const float* __restrict__ X,
                                              int p) {
    int c = blockIdx.y;
    if (c >= d_kval) return;
    int tile = blockIdx.x;
    int ti = 0;
    while ((ti + 1) * (ti + 2) / 2 <= tile) ti++;
    int tj = tile - ti * (ti + 1) / 2;
    int a0 = ti * 128, b0 = tj * 128;
    int z = blockIdx.z;
    int cstart = d_cstart[c], ccnt = d_cnt[c];
    int sb = (int)((long long)ccnt * z / NSLICE);
    int se = (int)((long long)ccnt * (z + 1) / NSLICE);

    __shared__ __align__(16) float sA[32][132];
    __shared__ __align__(16) float sB[32][132];
    __shared__ int sidx[32];

    int tid = threadIdx.x;
    int tx = tid & 15, ty = tid >> 4;
    int lt = tid >> 3, lc = tid & 7;

    ull acc2[8][4];
#pragma unroll
    for (int i = 0; i < 8; i++)
#pragma unroll
        for (int q = 0; q < 4; q++) acc2[i][q] = 0ull;

    for (int base = sb; base < se; base += 32) {
        int nv = se - base;
        if (nv > 32) nv = 32;
        __syncthreads();
        if (tid < 32)
            sidx[tid] = (tid < nv) ? d_idx[cstart + base + tid] : -1;
        __syncthreads();
        {
            int s = sidx[lt];
            if (s >= 0) {
                const float* xr = X + (size_t)s * p;
#pragma unroll
                for (int q = 0; q < 4; q++) {
                    int col = lc * 16 + q * 4;
                    *(float4*)&sA[lt][col] = *(const float4*)&xr[a0 + col];
                    *(float4*)&sB[lt][col] = *(const float4*)&xr[b0 + col];
                }
            }
        }
        __syncthreads();

        for (int t = 0; t < nv; t++) {
            float a[8];
            ull ad[8], b2[4];
            *(float4*)&a[0] = *(const float4*)&sA[t][ty * 8];
            *(float4*)&a[4] = *(const float4*)&sA[t][ty * 8 + 4];
#pragma unroll
            for (int i = 0; i < 8; i++) ad[i] = dup2(a[i]);
#pragma unroll
            for (int q = 0; q < 4; q++)
                b2[q] = *(const ull*)&sB[t][tx * 2 + q * 32];
#pragma unroll
            for (int i = 0; i < 8; i++)
#pragma unroll
                for (int q = 0; q < 4; q++)
                    acc2[i][q] = ffma2(ad[i], b2[q], acc2[i][q]);
        }
    }

    float* G = d_Gk[z][c];
    int gi = a0 + ty * 8;
#pragma unroll
    for (int i = 0; i < 8; i++)
#pragma unroll
        for (int q = 0; q < 4; q++) {
            float2 v = unpk2(acc2[i][q]);
            int col = b0 + q * 32 + tx * 2;
            *(float2*)&G[(size_t)(gi + i) * P + col] = v;
        }
    if (ti != tj) {
#pragma unroll
        for (int i = 0; i < 8; i++)
#pragma unroll
            for (int q = 0; q < 4; q++) {
                float2 v = unpk2(acc2[i][q]);
                int col = b0 + q * 32 + tx * 2;
                G[(size_t)col * P + gi + i]       = v.x;
                G[(size_t)(col + 1) * P + gi + i] = v.y;
            }
    }
}

// --------- assemble ---------------------------------------------------------
__global__ __launch_bounds__(256) void k_assemble(int m, float pf) {
    int idx4 = blockIdx.x * blockDim.x + threadIdx.x;
    if (idx4 >= P * P / 4) return;
    int idx = idx4 * 4;
    int r = idx >> 9, c0 = idx & 511;
    int kv = d_kval;
    float dg[4];
#pragma unroll
    for (int q = 0; q < 4; q++) dg[q] = (r == c0 + q) ? 1.f : 0.f;
    float sum[4] = {0.f, 0.f, 0.f, 0.f};
    for (int j = 0; j < kv; j++) {
        float4 g0 = *(const float4*)&d_Gk[0][j][idx];
        float4 g1 = *(const float4*)&d_Gk[1][j][idx];
        float4 g2 = *(const float4*)&d_Gk[2][j][idx];
        float g[4];
        g[0] = g0.x + g1.x + g2.x; g[1] = g0.y + g1.y + g2.y;
        g[2] = g0.z + g1.z + g2.z; g[3] = g0.w + g1.w + g2.w;
        float scal = pf / (((float)d_cnt[j] + 1e-8f) * 0.01f);
        float4 o;
        o.x = dg[0] + scal * g[0]; o.y = dg[1] + scal * g[1];
        o.z = dg[2] + scal * g[2]; o.w = dg[3] + scal * g[3];
        *(float4*)&d_A[j][idx] = o;
#pragma unroll
        for (int q = 0; q < 4; q++) sum[q] += g[q];
    }
    float scalar = pf / ((float)m * 0.01f);
    float4 o;
    o.x = dg[0] + scalar * sum[0]; o.y = dg[1] + scalar * sum[1];
    o.z = dg[2] + scalar * sum[2]; o.w = dg[3] + scalar * sum[3];
    *(float4*)&d_A[kv][idx] = o;
}

// ---- diag core: factor 64x64 in sD (pitch 65), logdet, Z=L^-1 into sZ -----
// scratch: sdinv at scr[0..64), sRed [64..128), sW8 [128..640)
__device__ void diag_core(int mb, int sidx, int tid, float* sD, float* sZ,
                          float* scr) {
    float* sdinv = scr;
    float* sRed  = scr + 64;
    float* sW8   = scr + 128;
    bool needZ = (sidx < NSTEP - 1);
    if (needZ)
        for (int l = tid; l < NB * 65; l += 256) sZ[l] = 0.f;
    __syncthreads();

#pragma unroll 1
    for (int b = 0; b < NB; b += 8) {
        if (tid == 0) {
            float a[8][8];
#pragma unroll
            for (int i = 0; i < 8; i++)
#pragma unroll
                for (int u = 0; u <= i; u++)
                    a[i][u] = sD[(b + i) * 65 + b + u];
#pragma unroll
            for (int t = 0; t < 8; t++) {
                float rinv = rsqrtf(a[t][t]);
                a[t][t] *= rinv;
                sdinv[b + t] = rinv;
#pragma unroll
                for (int i = t + 1; i < 8; i++) a[i][t] *= rinv;
#pragma unroll
                for (int u = t + 1; u < 8; u++)
#pragma unroll
                    for (int i = u; i < 8; i++)
                        a[i][u] = fmaf(-a[i][t], a[u][t], a[i][u]);
            }
#pragma unroll
            for (int i = 0; i < 8; i++)
#pragma unroll
                for (int u = 0; u <= i; u++)
                    sD[(b + i) * 65 + b + u] = a[i][u];
        }
        __syncthreads();

        int rows = NB - b - 8;
        if (rows > 0) {
            if (tid < rows) {
                int r = b + 8 + tid;
                float x[8];
#pragma unroll
                for (int t = 0; t < 8; t++) x[t] = sD[r * 65 + b + t];
#pragma unroll
                for (int t = 0; t < 8; t++) {
                    float v = x[t];
#pragma unroll
                    for (int u = 0; u < t; u++)
                        v = fmaf(-x[u], sD[(b + t) * 65 + b + u], v);
                    x[t] = v * sdinv[b + t];
                }
#pragma unroll
                for (int t = 0; t < 8; t++) sD[r * 65 + b + t] = x[t];
            }
            __syncthreads();

            int total = rows << 6;
            for (int l = tid; l < total; l += 256) {
                int i = b + 8 + (l >> 6), u = l & 63;
                if (u >= b + 8) {
                    float acc = sD[i * 65 + u];
#pragma unroll
                    for (int t = 0; t < 8; t++)
                        acc = fmaf(-sD[i * 65 + b + t], sD[u * 65 + b + t],
                                   acc);
                    sD[i * 65 + u] = acc;
                }
            }
        }
        __syncthreads();
    }

    if (tid < NB) sRed[tid] = logf(sD[tid * 65 + tid]);
    __syncthreads();
    if (tid < 32) {
        double lsum = (double)sRed[tid] + (double)sRed[tid + 32];
#pragma unroll
        for (int o = 16; o > 0; o >>= 1)
            lsum += __shfl_down_sync(0xffffffffu, lsum, o);
        if (tid == 0) d_hldd[mb] += lsum;
    }
    if (!needZ) return;

    // Z = L^{-1}: rank-8 panels
    for (int b = 0; b < NB; b += 8) {
        {
            int t0 = tid >> 6;
            int j = tid & 63;
#pragma unroll
            for (int pass = 0; pass < 2; pass++) {
                int t = t0 + pass * 4;
                float acc = 0.f;
                for (int u = 0; u < b; u++)
                    acc = fmaf(sD[(b + t) * 65 + u], sZ[u * 65 + j], acc);
                sW8[t * 64 + j] = acc;
            }
        }
        __syncthreads();
        if (tid < 64) {
            int j = tid;
#pragma unroll
            for (int t = 0; t < 8; t++) {
                int r = b + t;
                if (j <= r) {
                    float v = ((r == j) ? 1.f : 0.f) - sW8[t * 64 + j];
#pragma unroll
                    for (int u = 0; u < 8; u++) {
                        if (u < t)
                            v = fmaf(-sD[r * 65 + b + u], sZ[(b + u) * 65 + j],
                                     v);
                    }
                    sZ[r * 65 + j] = v * sdinv[r];
                }
            }
        }
        __syncthreads();
    }
}

// ---- single 64x64x64 tile GEMM: acc2 = Wi^T * Wj (K-major rows) -----------
__device__ __forceinline__ void tile_gemm(const float* sWi, const float* sWj,
                                          int tx, int ty, ull acc2[4][2]) {
#pragma unroll
    for (int i = 0; i < 4; i++) { acc2[i][0] = 0ull; acc2[i][1] = 0ull; }
#pragma unroll 8
    for (int t = 0; t < NB; t++) {
        float4 av = *(const float4*)&sWi[t * DP + ty * 4];
        float4 bv = *(const float4*)&sWj[t * DP + tx * 4];
        ull b0 = pack2(bv.x, bv.y), b1 = pack2(bv.z, bv.w);
        ull a0 = dup2(av.x), a1 = dup2(av.y);
        ull a2 = dup2(av.z), a3 = dup2(av.w);
        acc2[0][0] = ffma2(a0, b0, acc2[0][0]);
        acc2[0][1] = ffma2(a0, b1, acc2[0][1]);
        acc2[1][0] = ffma2(a1, b0, acc2[1][0]);
        acc2[1][1] = ffma2(a1, b1, acc2[1][1]);
        acc2[2][0] = ffma2(a2, b0, acc2[2][0]);
        acc2[2][1] = ffma2(a2, b1, acc2[2][1]);
        acc2[3][0] = ffma2(a3, b0, acc2[3][0]);
        acc2[3][1] = ffma2(a3, b1, acc2[3][1]);
    }
}

// ---- k_chol: persistent W-panel Cholesky, all steps in ONE launch ---------
// smem map (floats): sW [0,4352) | sAT/sD [4352,8704) | sZ [8704,12864)
__global__ __launch_bounds__(256) void k_chol(float* out, int m) {
    int cx = blockIdx.x;
    int mb = blockIdx.y;
    if (mb > d_kval) return;
    extern __shared__ float fs[];
    int tid = threadIdx.x;
    int tx = tid & 15, ty = tid >> 4;
    float* A  = d_A[mb];
    float* Zg = d_Z[mb];

    float* sW  = fs;
    float* sAT = fs + 4352;       // aliases sD
    float* sD  = fs + 4352;
    float* sZ  = fs + 8704;

    // ---- step 0 diag on CTA0 ----
    if (cx == 0) {
        for (int l = tid; l < NB * NB; l += 256) {
            int r = l >> 6, c = l & 63;
            sD[r * 65 + c] = A[(size_t)r * P + c];
        }
        __syncthreads();
        diag_core(mb, 0, tid, sD, sZ, fs);
        for (int q = tid; q < NB * 65 / 4; q += 256)
            *(float4*)&Zg[q * 4] = *(const float4*)&sZ[q * 4];
    }
    int ep = 1;
    mbar(mb, NCTA * ep); ep++;     // Z(0) ready

    for (int s = 0; s < NSTEP - 1; s++) {
        int nblk = NSTEP - 1 - s;
        int ntile = nblk * (nblk + 1) / 2;
        int sc = s * NB;

        // ---- W phase: CTA j computes W_j = Z * A_j^T ----
        if (cx < nblk) {
            if (cx != 0) {
                for (int q = tid; q < NB * 65 / 4; q += 256)
                    *(float4*)&sZ[q * 4] = *(const float4*)&Zg[q * 4];
            }
            // transpose-load A panel rows [sc+NB+cx*NB, +64) cols [sc, sc+64)
            {
                int r0 = sc + NB + cx * NB;
                int j = tid >> 2, u0 = (tid & 3) * 16;
                const float* row = &A[(size_t)(r0 + j) * P + sc];
#pragma unroll
                for (int q4 = 0; q4 < 4; q4++) {
                    float4 v = *(const float4*)&row[u0 + q4 * 4];
                    int u = u0 + q4 * 4;
                    sAT[(u + 0) * DP + j] = v.x;
                    sAT[(u + 1) * DP + j] = v.y;
                    sAT[(u + 2) * DP + j] = v.z;
                    sAT[(u + 3) * DP + j] = v.w;
                }
            }
            __syncthreads();
            // W[t][c] = sum_u Z[t][u] * AT[u][c]
            ull acc2[4][2];
#pragma unroll
            for (int i = 0; i < 4; i++) { acc2[i][0] = 0ull; acc2[i][1] = 0ull; }
#pragma unroll 8
            for (int u = 0; u < NB; u++) {
                float4 bv = *(const float4*)&sAT[u * DP + tx * 4];
                ull b0 = pack2(bv.x, bv.y), b1 = pack2(bv.z, bv.w);
                ull a0 = dup2(sZ[(ty * 4 + 0) * 65 + u]);
                ull a1 = dup2(sZ[(ty * 4 + 1) * 65 + u]);
                ull a2 = dup2(sZ[(ty * 4 + 2) * 65 + u]);
                ull a3 = dup2(sZ[(ty * 4 + 3) * 65 + u]);
                acc2[0][0] = ffma2(a0, b0, acc2[0][0]);
                acc2[0][1] = ffma2(a0, b1, acc2[0][1]);
                acc2[1][0] = ffma2(a1, b0, acc2[1][0]);
                acc2[1][1] = ffma2(a1, b1, acc2[1][1]);
                acc2[2][0] = ffma2(a2, b0, acc2[2][0]);
                acc2[2][1] = ffma2(a2, b1, acc2[2][1]);
                acc2[3][0] = ffma2(a3, b0, acc2[3][0]);
                acc2[3][1] = ffma2(a3, b1, acc2[3][1]);
            }
            __syncthreads();   // sAT reads done before any reuse
            float* Wg = d_W[mb][cx];
#pragma unroll
            for (int q = 0; q < 4; q++) {
                float2 lo = unpk2(acc2[q][0]), hi = unpk2(acc2[q][1]);
                float4 v; v.x = lo.x; v.y = lo.y; v.z = hi.x; v.w = hi.y;
                int off = (ty * 4 + q) * DP + tx * 4;
                *(float4*)&sW[off] = v;     // local copy (CTA0 uses; others harmless)
                *(float4*)&Wg[off] = v;
            }
        }
        mbar(mb, NCTA * ep); ep++;     // W ready (+ prior trailing visible)

        // ---- T phase ----
        if (cx == 0) {
            // tile(0,0): C00 = A00 - W0^T W0 -> sD, then fused diag(s+1)
            ull acc2[4][2];
            tile_gemm(sW, sW, tx, ty, acc2);
            int r0 = sc + NB;
#pragma unroll
            for (int q = 0; q < 4; q++) {
                float2 lo = unpk2(acc2[q][0]), hi = unpk2(acc2[q][1]);
                const float* row = &A[(size_t)(r0 + ty * 4 + q) * P + r0 + tx * 4];
                float4 v = *(const float4*)row;
                int rr = ty * 4 + q, cc = tx * 4;
                sD[rr * 65 + cc + 0] = v.x - lo.x;
                sD[rr * 65 + cc + 1] = v.y - lo.y;
                sD[rr * 65 + cc + 2] = v.z - hi.x;
                sD[rr * 65 + cc + 3] = v.w - hi.y;
            }
            __syncthreads();
            diag_core(mb, s + 1, tid, sD, sZ, fs);
            if (s + 1 < NSTEP - 1) {
                for (int q = tid; q < NB * 65 / 4; q += 256)
                    *(float4*)&Zg[q * 4] = *(const float4*)&sZ[q * 4];
            }
        } else {
            for (int l = cx; l < ntile; l += NCTA - 1) {
                int ti = 0;
                while ((ti + 1) * (ti + 2) / 2 <= l) ti++;
                int tj = l - ti * (ti + 1) / 2;
                __syncthreads();
                {
                    const float* Wi = d_W[mb][ti];
                    for (int q = tid; q < NB * DP / 4; q += 256)
                        *(float4*)&sW[q * 4] = *(const float4*)&Wi[q * 4];
                }
                const float* sWj = sW;
                if (ti != tj) {
                    const float* Wj = d_W[mb][tj];
                    for (int q = tid; q < NB * DP / 4; q += 256)
                        *(float4*)&sAT[q * 4] = *(const float4*)&Wj[q * 4];
                    sWj = sAT;
                }
                __syncthreads();
                ull acc2[4][2];
                tile_gemm(sW, sWj, tx, ty, acc2);
                int ri = sc + NB + ti * NB, rj = sc + NB + tj * NB;
#pragma unroll
                for (int q = 0; q < 4; q++) {
                    float2 lo = unpk2(acc2[q][0]), hi = unpk2(acc2[q][1]);
                    float* row = &A[(size_t)(ri + ty * 4 + q) * P + rj + tx * 4];
                    float4 v = *(float4*)row;
                    v.x -= lo.x; v.y -= lo.y; v.z -= hi.x; v.w -= hi.y;
                    *(float4*)row = v;
                }
            }
        }
        mbar(mb, NCTA * ep); ep++;     // trailing done
    }

    // ---- finalize ----
    if (cx == 0 && tid == 0) {
        rel_add(&d_done);
        if (mb == 0) {
            int kv = d_kval;
            while (acq_ld(&d_done) < kv + 1) { }
            double comp = 0.0;
            for (int j = 0; j < kv; j++) {
                double trPi = (double)d_cnt[j] + 1e-8;
                comp += d_hldd[j] * trPi / (double)m;
            }
            out[0] = (float)d_hldd[kv];
            out[1] = (float)comp;
            d_lbar = 0;   // reset labels barrier for next graph replay
        }
    }
}

// ---------------- launch ----------------------------------------------------
extern "C" void kernel_launch(void* const* d_in, const int* in_sizes, int n_in,
                              void* d_out, int out_size) {
    const float* X    = (const float*)d_in[0];
    const void*  Y    = d_in[1];
    const int*   ncls = (n_in >= 3) ? (const int*)d_in[2] : nullptr;
    int m = in_sizes[1];
    int p = in_sizes[0] / m;          // 512
    float* out = (float*)d_out;
    (void)out_size;
    int nchunk = (m + 255) / 256;

    cudaFuncSetAttribute(k_chol, cudaFuncAttributeMaxDynamicSharedMemorySize,
                         FT_SMEM_BYTES);

    k_labels<<<nchunk, 256>>>(Y, ncls, m, nchunk);
    k_gram<<<dim3(10, K_MAX, NSLICE), 256>>>(X, p);
    k_assemble<<<(P * P / 4 + 255) / 256, 256>>>(m, (float)p);
    k_chol<<<dim3(NCTA, NM), 256, FT_SMEM_BYTES>>>(out, m);
}

// round 12
// speedup vs baseline: 1.4392x; 1.0085x over previous
#include <cuda_runtime.h>
#include <math.h>

#define P       512
#define K_MAX   16
#define NM      (K_MAX + 1)
#define M_CAP   65536
#define NCH_MAX 256
#define NB      64
#define NSTEP   (P / NB)      // 8
#define NSLICE  3
#define DP      68
#define NCTA    15            // CTAs per matrix in persistent chol
#define REG     4352          // smem region stride (floats) = 64*68

#define FT_SMEM_BYTES (4 * REG * 4)   // 69632 B

typedef unsigned long long ull;

// ---------------- f32x2 packed helpers (Blackwell sm_103a) -----------------
__device__ __forceinline__ ull ffma2(ull a, ull b, ull c) {
    ull d;
    asm("fma.rn.f32x2 %0, %1, %2, %3;" : "=l"(d) : "l"(a), "l"(b), "l"(c));
    return d;
}
__device__ __forceinline__ ull dup2(float x) {
    ull r; unsigned xb = __float_as_uint(x);
    asm("mov.b64 %0, {%1, %2};" : "=l"(r) : "r"(xb), "r"(xb));
    return r;
}
__device__ __forceinline__ ull pack2(float lo, float hi) {
    ull r;
    asm("mov.b64 %0, {%1, %2};" : "=l"(r) : "f"(lo), "f"(hi));
    return r;
}
__device__ __forceinline__ float2 unpk2(ull v) {
    float2 r;
    asm("mov.b64 {%0, %1}, %2;" : "=f"(r.x), "=f"(r.y) : "l"(v));
    return r;
}

// ---------------- device scratch -------------------------------------------
__device__ int    d_cnt[K_MAX];
__device__ int    d_kval;
__device__ int    d_idx[M_CAP];
__device__ int    d_bh[NCH_MAX][K_MAX];
__device__ int    d_boff[NCH_MAX][K_MAX];
__device__ int    d_cstart[K_MAX];
__device__ int    d_lbar;
__device__ int    d_bar[NM];
__device__ int    d_done;
__device__ float  d_Gk[NSLICE][K_MAX][P * P];
__device__ float  d_A[NM][P * P];
__device__ float  d_Z[NM][NB * 65];
__device__ double d_hldd[NM];

// ---------------- release/acquire spin barriers ----------------------------
__device__ __forceinline__ void rel_add(int* p) {
    int d;
    asm volatile("atom.release.gpu.add.s32 %0, [%1], 1;"
                 : "=r"(d) : "l"(p) : "memory");
}
__device__ __forceinline__ int acq_ld(const int* p) {
    int v;
    asm volatile("ld.acquire.gpu.s32 %0, [%1];" : "=r"(v) : "l"(p) : "memory");
    return v;
}
__device__ __forceinline__ void gbar(int nb, int ep) {
    __syncthreads();
    if (threadIdx.x == 0) {
        rel_add(&d_lbar);
        while (acq_ld(&d_lbar) < nb * ep) { }
    }
    __syncthreads();
}
__device__ __forceinline__ void mbar(int mb, int target) {
    __syncthreads();
    if (threadIdx.x == 0) {
        rel_add(&d_bar[mb]);
        while (acq_ld(&d_bar[mb]) < target) { }
    }
    __syncthreads();
}

// ------- k_labels: dtype detect + hist + scan + stable scatter (1 launch) --
__global__ __launch_bounds__(256) void k_labels(const void* __restrict__ Y,
                                                const int* ncls, int m,
                                                int nchunk) {
    __shared__ int sh[K_MAX];
    __shared__ int swh[8 * K_MAX];
    __shared__ int nzf;
    int tid = threadIdx.x;
    int b = blockIdx.x;
    if (tid == 0) nzf = 0;
    if (tid < K_MAX) sh[tid] = 0;
    __syncthreads();

    int lim = m / 2; if (lim > 512) lim = 512;
    int found = 0;
    for (int i = tid; i < lim; i += 256)
        if (((const int*)Y)[2 * i + 1] != 0) found = 1;
    if (__any_sync(0xffffffffu, found)) {
        if ((tid & 31) == 0) atomicOr(&nzf, 1);
    }
    __syncthreads();
    int is64 = nzf ? 0 : 1;

    int i = b * 256 + tid;
    int c = -1;
    if (i < m) {
        c = is64 ? (int)((const long long*)Y)[i] : ((const int*)Y)[i];
        if (c < 0 || c >= K_MAX) c = 0;
        atomicAdd(&sh[c], 1);
    }
    __syncthreads();
    if (tid < K_MAX) d_bh[b][tid] = sh[tid];

    gbar(nchunk, 1);

    if (b == 0) {
        if (tid < K_MAX) {
            int run = 0;
            for (int bb = 0; bb < nchunk; bb++) {
                d_boff[bb][tid] = run;
                run += d_bh[bb][tid];
            }
            d_cnt[tid] = run;
            sh[tid] = run;
        }
        __syncthreads();
        if (tid == 0) {
            int run = 0;
            for (int cc = 0; cc < K_MAX; cc++) {
                d_cstart[cc] = run;
                run += sh[cc];
            }
            int k = ncls ? *ncls : 10;
            if (k < 1) k = 1;
            if (k > K_MAX) k = K_MAX;
            d_kval = k;
            d_done = 0;
        }
        if (tid < NM) { d_hldd[tid] = 0.0; d_bar[tid] = 0; }
    }

    gbar(nchunk, 2);

    if (tid < 8 * K_MAX) swh[tid] = 0;
    __syncthreads();
    int lane = tid & 31, w = tid >> 5;
    unsigned mask = __match_any_sync(0xffffffffu, c);
    int rin = __popc(mask & ((1u << lane) - 1u));
    int leader = __ffs(mask) - 1;
    if (c >= 0 && lane == leader) swh[w * K_MAX + c] = __popc(mask);
    __syncthreads();
    if (c >= 0) {
        int pre = 0;
        for (int w2 = 0; w2 < w; w2++) pre += swh[w2 * K_MAX + c];
        d_idx[d_cstart[c] + d_boff[b][c] + pre + rin] = i;
    }
}

// ------- per-class Gram: dense gather over sorted class range --------------
__global__ __launch_bounds__(256) void k_gram(const float* __restrict__ X,
                                              int p) {
    int c = blockIdx.y;
    if (c >= d_kval) return;
    int tile = blockIdx.x;
    int ti = 0;
    while ((ti + 1) * (ti + 2) / 2 <= tile) ti++;
    int tj = tile - ti * (ti + 1) / 2;
    int a0 = ti * 128, b0 = tj * 128;
    int z = blockIdx.z;
    int cstart = d_cstart[c], ccnt = d_cnt[c];
    int sb = (int)((long long)ccnt * z / NSLICE);
    int se = (int)((long long)ccnt * (z + 1) / NSLICE);

    __shared__ __align__(16) float sA[32][132];
    __shared__ __align__(16) float sB[32][132];
    __shared__ int sidx[32];

    int tid = threadIdx.x;
    int tx = tid & 15, ty = tid >> 4;
    int lt = tid >> 3, lc = tid & 7;

    ull acc2[8][4];
#pragma unroll
    for (int i = 0; i < 8; i++)
#pragma unroll
        for (int q = 0; q < 4; q++) acc2[i][q] = 0ull;

    for (int base = sb; base < se; base += 32) {
        int nv = se - base;
        if (nv > 32) nv = 32;
        __syncthreads();
        if (tid < 32)
            sidx[tid] = (tid < nv) ? d_idx[cstart + base + tid] : -1;
        __syncthreads();
        {
            int s = sidx[lt];
            if (s >= 0) {
                const float* xr = X + (size_t)s * p;
#pragma unroll
                for (int q = 0; q < 4; q++) {
                    int col = lc * 16 + q * 4;
                    *(float4*)&sA[lt][col] = *(const float4*)&xr[a0 + col];
                    *(float4*)&sB[lt][col] = *(const float4*)&xr[b0 + col];
                }
            }
        }
        __syncthreads();

        for (int t = 0; t < nv; t++) {
            float a[8];
            ull ad[8], b2[4];
            *(float4*)&a[0] = *(const float4*)&sA[t][ty * 8];
            *(float4*)&a[4] = *(const float4*)&sA[t][ty * 8 + 4];
#pragma unroll
            for (int i = 0; i < 8; i++) ad[i] = dup2(a[i]);
#pragma unroll
            for (int q = 0; q < 4; q++)
                b2[q] = *(const ull*)&sB[t][tx * 2 + q * 32];
#pragma unroll
            for (int i = 0; i < 8; i++)
#pragma unroll
                for (int q = 0; q < 4; q++)
                    acc2[i][q] = ffma2(ad[i], b2[q], acc2[i][q]);
        }
    }

    float* G = d_Gk[z][c];
    int gi = a0 + ty * 8;
#pragma unroll
    for (int i = 0; i < 8; i++)
#pragma unroll
        for (int q = 0; q < 4; q++) {
            float2 v = unpk2(acc2[i][q]);
            int col = b0 + q * 32 + tx * 2;
            *(float2*)&G[(size_t)(gi + i) * P + col] = v;
        }
    if (ti != tj) {
#pragma unroll
        for (int i = 0; i < 8; i++)
#pragma unroll
            for (int q = 0; q < 4; q++) {
                float2 v = unpk2(acc2[i][q]);
                int col = b0 + q * 32 + tx * 2;
                G[(size_t)col * P + gi + i]       = v.x;
                G[(size_t)(col + 1) * P + gi + i] = v.y;
            }
    }
}

// --------- assemble ---------------------------------------------------------
__global__ __launch_bounds__(256) void k_assemble(int m, float pf) {
    int idx4 = blockIdx.x * blockDim.x + threadIdx.x;
    if (idx4 >= P * P / 4) return;
    int idx = idx4 * 4;
    int r = idx >> 9, c0 = idx & 511;
    int kv = d_kval;
    float dg[4];
#pragma unroll
    for (int q = 0; q < 4; q++) dg[q] = (r == c0 + q) ? 1.f : 0.f;
    float sum[4] = {0.f, 0.f, 0.f, 0.f};
    for (int j = 0; j < kv; j++) {
        float4 g0 = *(const float4*)&d_Gk[0][j][idx];
        float4 g1 = *(const float4*)&d_Gk[1][j][idx];
        float4 g2 = *(const float4*)&d_Gk[2][j][idx];
        float g[4];
        g[0] = g0.x + g1.x + g2.x; g[1] = g0.y + g1.y + g2.y;
        g[2] = g0.z + g1.z + g2.z; g[3] = g0.w + g1.w + g2.w;
        float scal = pf / (((float)d_cnt[j] + 1e-8f) * 0.01f);
        float4 o;
        o.x = dg[0] + scal * g[0]; o.y = dg[1] + scal * g[1];
        o.z = dg[2] + scal * g[2]; o.w = dg[3] + scal * g[3];
        *(float4*)&d_A[j][idx] = o;
#pragma unroll
        for (int q = 0; q < 4; q++) sum[q] += g[q];
    }
    float scalar = pf / ((float)m * 0.01f);
    float4 o;
    o.x = dg[0] + scalar * sum[0]; o.y = dg[1] + scalar * sum[1];
    o.z = dg[2] + scalar * sum[2]; o.w = dg[3] + scalar * sum[3];
    *(float4*)&d_A[kv][idx] = o;
}

// ---- diag core: factor 64x64 in sD (pitch 65), logdet, Z=L^-1 into sZ -----
// scratch scr: sdinv [0,64), sRed [64,128), sW8 [128,640)
__device__ void diag_core(int mb, int sidx, int tid, float* sD, float* sZ,
                          float* scr) {
    float* sdinv = scr;
    float* sRed  = scr + 64;
    float* sW8   = scr + 128;
    bool needZ = (sidx < NSTEP - 1);
    if (needZ)
        for (int l = tid; l < NB * 65; l += 256) sZ[l] = 0.f;
    __syncthreads();

#pragma unroll 1
    for (int b = 0; b < NB; b += 8) {
        if (tid == 0) {
            float a[8][8];
#pragma unroll
            for (int i = 0; i < 8; i++)
#pragma unroll
                for (int u = 0; u <= i; u++)
                    a[i][u] = sD[(b + i) * 65 + b + u];
#pragma unroll
            for (int t = 0; t < 8; t++) {
                float rinv = rsqrtf(a[t][t]);
                a[t][t] *= rinv;
                sdinv[b + t] = rinv;
#pragma unroll
                for (int i = t + 1; i < 8; i++) a[i][t] *= rinv;
#pragma unroll
                for (int u = t + 1; u < 8; u++)
#pragma unroll
                    for (int i = u; i < 8; i++)
                        a[i][u] = fmaf(-a[i][t], a[u][t], a[i][u]);
            }
#pragma unroll
            for (int i = 0; i < 8; i++)
#pragma unroll
                for (int u = 0; u <= i; u++)
                    sD[(b + i) * 65 + b + u] = a[i][u];
        }
        __syncthreads();

        int rows = NB - b - 8;
        if (rows > 0) {
            if (tid < rows) {
                int r = b + 8 + tid;
                float x[8];
#pragma unroll
                for (int t = 0; t < 8; t++) x[t] = sD[r * 65 + b + t];
#pragma unroll
                for (int t = 0; t < 8; t++) {
                    float v = x[t];
#pragma unroll
                    for (int u = 0; u < t; u++)
                        v = fmaf(-x[u], sD[(b + t) * 65 + b + u], v);
                    x[t] = v * sdinv[b + t];
                }
#pragma unroll
                for (int t = 0; t < 8; t++) sD[r * 65 + b + t] = x[t];
            }
            __syncthreads();

            int total = rows << 6;
            for (int l = tid; l < total; l += 256) {
                int i = b + 8 + (l >> 6), u = l & 63;
                if (u >= b + 8) {
                    float acc = sD[i * 65 + u];
#pragma unroll
                    for (int t = 0; t < 8; t++)
                        acc = fmaf(-sD[i * 65 + b + t], sD[u * 65 + b + t],
                                   acc);
                    sD[i * 65 + u] = acc;
                }
            }
        }
        __syncthreads();
    }

    if (tid < NB) sRed[tid] = logf(sD[tid * 65 + tid]);
    __syncthreads();
    if (tid < 32) {
        double lsum = (double)sRed[tid] + (double)sRed[tid + 32];
#pragma unroll
        for (int o = 16; o > 0; o >>= 1)
            lsum += __shfl_down_sync(0xffffffffu, lsum, o);
        if (tid == 0) d_hldd[mb] += lsum;
    }
    if (!needZ) return;

    for (int b = 0; b < NB; b += 8) {
        {
            int t0 = tid >> 6;
            int j = tid & 63;
#pragma unroll
            for (int pass = 0; pass < 2; pass++) {
                int t = t0 + pass * 4;
                float acc = 0.f;
                for (int u = 0; u < b; u++)
                    acc = fmaf(sD[(b + t) * 65 + u], sZ[u * 65 + j], acc);
                sW8[t * 64 + j] = acc;
            }
        }
        __syncthreads();
        if (tid < 64) {
            int j = tid;
#pragma unroll
            for (int t = 0; t < 8; t++) {
                int r = b + t;
                if (j <= r) {
                    float v = ((r == j) ? 1.f : 0.f) - sW8[t * 64 + j];
#pragma unroll
                    for (int u = 0; u < 8; u++) {
                        if (u < t)
                            v = fmaf(-sD[r * 65 + b + u], sZ[(b + u) * 65 + j],
                                     v);
                    }
                    sZ[r * 65 + j] = v * sdinv[r];
                }
            }
        }
        __syncthreads();
    }
}

// ---- W GEMM: sWout[t][c] = sum_u Z[t][u] * AT[u][c]  (Z pitch 65, DP out) -
__device__ __forceinline__ void w_gemm(const float* sZ, const float* sAT,
                                       float* sWout, int tx, int ty) {
    ull acc2[4][2];
#pragma unroll
    for (int i = 0; i < 4; i++) { acc2[i][0] = 0ull; acc2[i][1] = 0ull; }
#pragma unroll 8
    for (int u = 0; u < NB; u++) {
        float4 bv = *(const float4*)&sAT[u * DP + tx * 4];
        ull b0 = pack2(bv.x, bv.y), b1 = pack2(bv.z, bv.w);
        ull a0 = dup2(sZ[(ty * 4 + 0) * 65 + u]);
        ull a1 = dup2(sZ[(ty * 4 + 1) * 65 + u]);
        ull a2 = dup2(sZ[(ty * 4 + 2) * 65 + u]);
        ull a3 = dup2(sZ[(ty * 4 + 3) * 65 + u]);
        acc2[0][0] = ffma2(a0, b0, acc2[0][0]);
        acc2[0][1] = ffma2(a0, b1, acc2[0][1]);
        acc2[1][0] = ffma2(a1, b0, acc2[1][0]);
        acc2[1][1] = ffma2(a1, b1, acc2[1][1]);
        acc2[2][0] = ffma2(a2, b0, acc2[2][0]);
        acc2[2][1] = ffma2(a2, b1, acc2[2][1]);
        acc2[3][0] = ffma2(a3, b0, acc2[3][0]);
        acc2[3][1] = ffma2(a3, b1, acc2[3][1]);
    }
#pragma unroll
    for (int q = 0; q < 4; q++) {
        float2 lo = unpk2(acc2[q][0]), hi = unpk2(acc2[q][1]);
        float4 v; v.x = lo.x; v.y = lo.y; v.z = hi.x; v.w = hi.y;
        *(float4*)&sWout[(ty * 4 + q) * DP + tx * 4] = v;
    }
}

// ---- transpose-load 64x64 A panel into sAT (pitch DP) ---------------------
__device__ __forceinline__ void at_load(const float* A, int r0, int sc,
                                        float* sAT, int tid) {
    int j = tid >> 2, u0 = (tid & 3) * 16;
    const float* row = &A[(size_t)(r0 + j) * P + sc];
#pragma unroll
    for (int q4 = 0; q4 < 4; q4++) {
        float4 v = *(const float4*)&row[u0 + q4 * 4];
        int u = u0 + q4 * 4;
        sAT[(u + 0) * DP + j] = v.x;
        sAT[(u + 1) * DP + j] = v.y;
        sAT[(u + 2) * DP + j] = v.z;
        sAT[(u + 3) * DP + j] = v.w;
    }
}

// ---- tile GEMM: acc2 = Wi^T * Wj -----------------------------------------
__device__ __forceinline__ void tile_gemm(const float* sWi, const float* sWj,
                                          int tx, int ty, ull acc2[4][2]) {
#pragma unroll
    for (int i = 0; i < 4; i++) { acc2[i][0] = 0ull; acc2[i][1] = 0ull; }
#pragma unroll 8
    for (int t = 0; t < NB; t++) {
        float4 av = *(const float4*)&sWi[t * DP + ty * 4];
        float4 bv = *(const float4*)&sWj[t * DP + tx * 4];
        ull b0 = pack2(bv.x, bv.y), b1 = pack2(bv.z, bv.w);
        ull a0 = dup2(av.x), a1 = dup2(av.y);
        ull a2 = dup2(av.z), a3 = dup2(av.w);
        acc2[0][0] = ffma2(a0, b0, acc2[0][0]);
        acc2[0][1] = ffma2(a0, b1, acc2[0][1]);
        acc2[1][0] = ffma2(a1, b0, acc2[1][0]);
        acc2[1][1] = ffma2(a1, b1, acc2[1][1]);
        acc2[2][0] = ffma2(a2, b0, acc2[2][0]);
        acc2[2][1] = ffma2(a2, b1, acc2[2][1]);
        acc2[3][0] = ffma2(a3, b0, acc2[3][0]);
        acc2[3][1] = ffma2(a3, b1, acc2[3][1]);
    }
}

// ---- k_chol: persistent, local-W Schur, ONE barrier per step --------------
// smem regions (floats): sZ=fs[0,REG) | sAT=fs[REG,2R) | sWi=[2R,3R) | sWj=[3R,4R)
__global__ __launch_bounds__(256) void k_chol(float* out, int m) {
    int cx = blockIdx.x;
    int mb = blockIdx.y;
    if (mb > d_kval) return;
    extern __shared__ float fs[];
    int tid = threadIdx.x;
    int tx = tid & 15, ty = tid >> 4;
    float* A  = d_A[mb];
    float* Zg = d_Z[mb];

    float* sZ  = fs;
    float* sAT = fs + REG;
    float* sWi = fs + 2 * REG;
    float* sWj = fs + 3 * REG;

    // ---- step 0 diag on CTA0 (sD aliases sAT region, scr aliases sWj) ----
    if (cx == 0) {
        float* sD = sAT;
        for (int l = tid; l < NB * NB; l += 256) {
            int r = l >> 6, c = l & 63;
            sD[r * 65 + c] = A[(size_t)r * P + c];
        }
        __syncthreads();
        diag_core(mb, 0, tid, sD, sZ, sWj);
        for (int q = tid; q < NB * 65 / 4; q += 256)
            *(float4*)&Zg[q * 4] = *(const float4*)&sZ[q * 4];
    }
    int ep = 1;
    mbar(mb, NCTA * ep); ep++;     // Z(0) ready

    for (int s = 0; s < NSTEP - 1; s++) {
        int nblk = NSTEP - 1 - s;
        int ntile = nblk * (nblk + 1) / 2;
        int sc = s * NB;

        if (cx == 0) {
            // W0 = Z * A0^T  (Z already resident in sZ)
            at_load(A, sc + NB, sc, sAT, tid);
            __syncthreads();
            w_gemm(sZ, sAT, sWi, tx, ty);
            __syncthreads();
            // tile00: sD = A00 - W0^T W0 (sD aliases sAT)
            ull acc2[4][2];
            tile_gemm(sWi, sWi, tx, ty, acc2);
            float* sD = sAT;
            int r0 = sc + NB;
#pragma unroll
            for (int q = 0; q < 4; q++) {
                float2 lo = unpk2(acc2[q][0]), hi = unpk2(acc2[q][1]);
                const float* row = &A[(size_t)(r0 + ty * 4 + q) * P + r0 + tx * 4];
                float4 v = *(const float4*)row;
                int rr = ty * 4 + q, cc = tx * 4;
                sD[rr * 65 + cc + 0] = v.x - lo.x;
                sD[rr * 65 + cc + 1] = v.y - lo.y;
                sD[rr * 65 + cc + 2] = v.z - hi.x;
                sD[rr * 65 + cc + 3] = v.w - hi.y;
            }
            __syncthreads();
            diag_core(mb, s + 1, tid, sD, sZ, sWj);
            if (s + 1 < NSTEP - 1) {
                for (int q = tid; q < NB * 65 / 4; q += 256)
                    *(float4*)&Zg[q * 4] = *(const float4*)&sZ[q * 4];
            }
        } else if (cx < ntile + 1) {
            // worker: load Z(s) once, then process its tiles with local W
            for (int q = tid; q < NB * 65 / 4; q += 256)
                *(float4*)&sZ[q * 4] = *(const float4*)&Zg[q * 4];
            // note: tiles l = cx, cx + (NCTA-1), ... ; l=0 is CTA0's
            for (int l = cx; l < ntile; l += NCTA - 1) {
                int ti = 0;
                while ((ti + 1) * (ti + 2) / 2 <= l) ti++;
                int tj = l - ti * (ti + 1) / 2;
                int ri = sc + NB + ti * NB, rj = sc + NB + tj * NB;

                __syncthreads();
                at_load(A, ri, sc, sAT, tid);
                __syncthreads();
                w_gemm(sZ, sAT, sWi, tx, ty);
                __syncthreads();
                const float* pWj = sWi;
                if (ti != tj) {
                    at_load(A, rj, sc, sAT, tid);
                    __syncthreads();
                    w_gemm(sZ, sAT, sWj, tx, ty);
                    pWj = sWj;
                }
                __syncthreads();
                ull acc2[4][2];
                tile_gemm(sWi, pWj, tx, ty, acc2);
#pragma unroll
                for (int q = 0; q < 4; q++) {
                    float2 lo = unpk2(acc2[q][0]), hi = unpk2(acc2[q][1]);
                    float* row = &A[(size_t)(ri + ty * 4 + q) * P + rj + tx * 4];
                    float4 v = *(float4*)row;
                    v.x -= lo.x; v.y -= lo.y; v.z -= hi.x; v.w -= hi.y;
                    *(float4*)row = v;
                }
            }
        }
        mbar(mb, NCTA * ep); ep++;     // trailing + Z(s+1) ready
    }

    // ---- finalize ----
    if (cx == 0 && tid == 0) {
        rel_add(&d_done);
        if (mb == 0) {
            int kv = d_kval;
            while (acq_ld(&d_done) < kv + 1) { }
            double comp = 0.0;
            for (int j = 0; j < kv; j++) {
                double trPi = (double)d_cnt[j] + 1e-8;
                comp += d_hldd[j] * trPi / (double)m;
            }
            out[0] = (float)d_hldd[kv];
            out[1] = (float)comp;
            d_lbar = 0;   // reset labels barrier for next graph replay
        }
    }
}

// ---------------- launch ----------------------------------------------------
extern "C" void kernel_launch(void* const* d_in, const int* in_sizes, int n_in,
                              void* d_out, int out_size) {
    const float* X    = (const float*)d_in[0];
    const void*  Y    = d_in[1];
    const int*   ncls = (n_in >= 3) ? (const int*)d_in[2] : nullptr;
    int m = in_sizes[1];
    int p = in_sizes[0] / m;          // 512
    float* out = (float*)d_out;
    (void)out_size;
    int nchunk = (m + 255) / 256;

    cudaFuncSetAttribute(k_chol, cudaFuncAttributeMaxDynamicSharedMemorySize,
                         FT_SMEM_BYTES);

    k_labels<<<nchunk, 256>>>(Y, ncls, m, nchunk);
    k_gram<<<dim3(10, K_MAX, NSLICE), 256>>>(X, p);
    k_assemble<<<(P * P / 4 + 255) / 256, 256>>>(m, (float)p);
    k_chol<<<dim3(NCTA, NM), 256, FT_SMEM_BYTES>>>(out, m);
}

// round 13
// speedup vs baseline: 1.4604x; 1.0147x over previous
#include <cuda_runtime.h>
#include <math.h>

#define P       512
#define K_MAX   16
#define NM      (K_MAX + 1)
#define M_CAP   65536
#define NCH_MAX 256
#define NB      64
#define NSTEP   (P / NB)      // 8
#define NSLICE  3
#define DP      68
#define NCTA    15            // CTAs per matrix in persistent chol
#define REG     4352          // smem region stride (floats) = 64*68

#define FT_SMEM_BYTES (4 * REG * 4)   // 69632 B

typedef unsigned long long ull;

// ---------------- f32x2 packed helpers (Blackwell sm_103a) -----------------
__device__ __forceinline__ ull ffma2(ull a, ull b, ull c) {
    ull d;
    asm("fma.rn.f32x2 %0, %1, %2, %3;" : "=l"(d) : "l"(a), "l"(b), "l"(c));
    return d;
}
__device__ __forceinline__ ull dup2(float x) {
    ull r; unsigned xb = __float_as_uint(x);
    asm("mov.b64 %0, {%1, %2};" : "=l"(r) : "r"(xb), "r"(xb));
    return r;
}
__device__ __forceinline__ ull pack2(float lo, float hi) {
    ull r;
    asm("mov.b64 %0, {%1, %2};" : "=l"(r) : "f"(lo), "f"(hi));
    return r;
}
__device__ __forceinline__ float2 unpk2(ull v) {
    float2 r;
    asm("mov.b64 {%0, %1}, %2;" : "=f"(r.x), "=f"(r.y) : "l"(v));
    return r;
}

// ---------------- device scratch -------------------------------------------
__device__ int    d_cnt[K_MAX];
__device__ int    d_kval;
__device__ int    d_idx[M_CAP];
__device__ int    d_bh[NCH_MAX][K_MAX];
__device__ int    d_boff[NCH_MAX][K_MAX];
__device__ int    d_cstart[K_MAX];
__device__ int    d_lbar;
__device__ int    d_bar[NM];
__device__ int    d_done;
__device__ int    d_wflag[NM][NSTEP - 1];     // per-panel epoch flags
__device__ float  d_Gk[NSLICE][K_MAX][P * P];
__device__ float  d_A[NM][P * P];
__device__ float  d_Z[NM][NB * 65];
__device__ float  d_W[NM][NSTEP - 1][NB * DP];
__device__ double d_hldd[NM];

// ---------------- release/acquire primitives -------------------------------
__device__ __forceinline__ void rel_add(int* p) {
    int d;
    asm volatile("atom.release.gpu.add.s32 %0, [%1], 1;"
                 : "=r"(d) : "l"(p) : "memory");
}
__device__ __forceinline__ void rel_st(int* p, int v) {
    asm volatile("st.release.gpu.s32 [%0], %1;" :: "l"(p), "r"(v) : "memory");
}
__device__ __forceinline__ int acq_ld(const int* p) {
    int v;
    asm volatile("ld.acquire.gpu.s32 %0, [%1];" : "=r"(v) : "l"(p) : "memory");
    return v;
}
__device__ __forceinline__ void gbar(int nb, int ep) {
    __syncthreads();
    if (threadIdx.x == 0) {
        rel_add(&d_lbar);
        while (acq_ld(&d_lbar) < nb * ep) { }
    }
    __syncthreads();
}
__device__ __forceinline__ void mbar(int mb, int target) {
    __syncthreads();
    if (threadIdx.x == 0) {
        rel_add(&d_bar[mb]);
        while (acq_ld(&d_bar[mb]) < target) { }
    }
    __syncthreads();
}
__device__ __forceinline__ void wflag_wait(int mb, int panel, int sval) {
    if (threadIdx.x == 0) {
        while (acq_ld(&d_wflag[mb][panel]) < sval) { }
    }
    __syncthreads();
}

// ------- k_labels: dtype detect + hist + scan + stable scatter (1 launch) --
__global__ __launch_bounds__(256) void k_labels(const void* __restrict__ Y,
                                                const int* ncls, int m,
                                                int nchunk) {
    __shared__ int sh[K_MAX];
    __shared__ int swh[8 * K_MAX];
    __shared__ int nzf;
    int tid = threadIdx.x;
    int b = blockIdx.x;
    if (tid == 0) nzf = 0;
    if (tid < K_MAX) sh[tid] = 0;
    __syncthreads();

    int lim = m / 2; if (lim > 512) lim = 512;
    int found = 0;
    for (int i = tid; i < lim; i += 256)
        if (((const int*)Y)[2 * i + 1] != 0) found = 1;
    if (__any_sync(0xffffffffu, found)) {
        if ((tid & 31) == 0) atomicOr(&nzf, 1);
    }
    __syncthreads();
    int is64 = nzf ? 0 : 1;

    int i = b * 256 + tid;
    int c = -1;
    if (i < m) {
        c = is64 ? (int)((const long long*)Y)[i] : ((const int*)Y)[i];
        if (c < 0 || c >= K_MAX) c = 0;
        atomicAdd(&sh[c], 1);
    }
    __syncthreads();
    if (tid < K_MAX) d_bh[b][tid] = sh[tid];

    gbar(nchunk, 1);

    if (b == 0) {
        if (tid < K_MAX) {
            int run = 0;
            for (int bb = 0; bb < nchunk; bb++) {
                d_boff[bb][tid] = run;
                run += d_bh[bb][tid];
            }
            d_cnt[tid] = run;
            sh[tid] = run;
        }
        __syncthreads();
        if (tid == 0) {
            int run = 0;
            for (int cc = 0; cc < K_MAX; cc++) {
                d_cstart[cc] = run;
                run += sh[cc];
            }
            int k = ncls ? *ncls : 10;
            if (k < 1) k = 1;
            if (k > K_MAX) k = K_MAX;
            d_kval = k;
            d_done = 0;
        }
        if (tid < NM) { d_hldd[tid] = 0.0; d_bar[tid] = 0; }
        if (tid < NM * (NSTEP - 1))
            ((int*)d_wflag)[tid] = 0;
    }

    gbar(nchunk, 2);

    if (tid < 8 * K_MAX) swh[tid] = 0;
    __syncthreads();
    int lane = tid & 31, w = tid >> 5;
    unsigned mask = __match_any_sync(0xffffffffu, c);
    int rin = __popc(mask & ((1u << lane) - 1u));
    int leader = __ffs(mask) - 1;
    if (c >= 0 && lane == leader) swh[w * K_MAX + c] = __popc(mask);
    __syncthreads();
    if (c >= 0) {
        int pre = 0;
        for (int w2 = 0; w2 < w; w2++) pre += swh[w2 * K_MAX + c];
        d_idx[d_cstart[c] + d_boff[b][c] + pre + rin] = i;
    }
}

// ------- per-class Gram: dense gather over sorted class range --------------
__global__ __launch_bounds__(256) void k_gram(const float* __restrict__ X,
                                              int p) {
    int c = blockIdx.y;
    if (c >= d_kval) return;
    int tile = blockIdx.x;
    int ti = 0;
    while ((ti + 1) * (ti + 2) / 2 <= tile) ti++;
    int tj = tile - ti * (ti + 1) / 2;
    int a0 = ti * 128, b0 = tj * 128;
    int z = blockIdx.z;
    int cstart = d_cstart[c], ccnt = d_cnt[c];
    int sb = (int)((long long)ccnt * z / NSLICE);
    int se = (int)((long long)ccnt * (z + 1) / NSLICE);

    __shared__ __align__(16) float sA[32][132];
    __shared__ __align__(16) float sB[32][132];
    __shared__ int sidx[32];

    int tid = threadIdx.x;
    int tx = tid & 15, ty = tid >> 4;
    int lt = tid >> 3, lc = tid & 7;

    ull acc2[8][4];
#pragma unroll
    for (int i = 0; i < 8; i++)
#pragma unroll
        for (int q = 0; q < 4; q++) acc2[i][q] = 0ull;

    for (int base = sb; base < se; base += 32) {
        int nv = se - base;
        if (nv > 32) nv = 32;
        __syncthreads();
        if (tid < 32)
            sidx[tid] = (tid < nv) ? d_idx[cstart + base + tid] : -1;
        __syncthreads();
        {
            int s = sidx[lt];
            if (s >= 0) {
                const float* xr = X + (size_t)s * p;
#pragma unroll
                for (int q = 0; q < 4; q++) {
                    int col = lc * 16 + q * 4;
                    *(float4*)&sA[lt][col] = *(const float4*)&xr[a0 + col];
                    *(float4*)&sB[lt][col] = *(const float4*)&xr[b0 + col];
                }
            }
        }
        __syncthreads();

        for (int t = 0; t < nv; t++) {
            float a[8];
            ull ad[8], b2[4];
            *(float4*)&a[0] = *(const float4*)&sA[t][ty * 8];
            *(float4*)&a[4] = *(const float4*)&sA[t][ty * 8 + 4];
#pragma unroll
            for (int i = 0; i < 8; i++) ad[i] = dup2(a[i]);
#pragma unroll
            for (int q = 0; q < 4; q++)
                b2[q] = *(const ull*)&sB[t][tx * 2 + q * 32];
#pragma unroll
            for (int i = 0; i < 8; i++)
#pragma unroll
                for (int q = 0; q < 4; q++)
                    acc2[i][q] = ffma2(ad[i], b2[q], acc2[i][q]);
        }
    }

    float* G = d_Gk[z][c];
    int gi = a0 + ty * 8;
#pragma unroll
    for (int i = 0; i < 8; i++)
#pragma unroll
        for (int q = 0; q < 4; q++) {
            float2 v = unpk2(acc2[i][q]);
            int col = b0 + q * 32 + tx * 2;
            *(float2*)&G[(size_t)(gi + i) * P + col] = v;
        }
    if (ti != tj) {
#pragma unroll
        for (int i = 0; i < 8; i++)
#pragma unroll
            for (int q = 0; q < 4; q++) {
                float2 v = unpk2(acc2[i][q]);
                int col = b0 + q * 32 + tx * 2;
                G[(size_t)col * P + gi + i]       = v.x;
                G[(size_t)(col + 1) * P + gi + i] = v.y;
            }
    }
}

// --------- assemble ---------------------------------------------------------
__global__ __launch_bounds__(256) void k_assemble(int m, float pf) {
    int idx4 = blockIdx.x * blockDim.x + threadIdx.x;
    if (idx4 >= P * P / 4) return;
    int idx = idx4 * 4;
    int r = idx >> 9, c0 = idx & 511;
    int kv = d_kval;
    float dg[4];
#pragma unroll
    for (int q = 0; q < 4; q++) dg[q] = (r == c0 + q) ? 1.f : 0.f;
    float sum[4] = {0.f, 0.f, 0.f, 0.f};
    for (int j = 0; j < kv; j++) {
        float4 g0 = *(const float4*)&d_Gk[0][j][idx];
        float4 g1 = *(const float4*)&d_Gk[1][j][idx];
        float4 g2 = *(const float4*)&d_Gk[2][j][idx];
        float g[4];
        g[0] = g0.x + g1.x + g2.x; g[1] = g0.y + g1.y + g2.y;
        g[2] = g0.z + g1.z + g2.z; g[3] = g0.w + g1.w + g2.w;
        float scal = pf / (((float)d_cnt[j] + 1e-8f) * 0.01f);
        float4 o;
        o.x = dg[0] + scal * g[0]; o.y = dg[1] + scal * g[1];
        o.z = dg[2] + scal * g[2]; o.w = dg[3] + scal * g[3];
        *(float4*)&d_A[j][idx] = o;
#pragma unroll
        for (int q = 0; q < 4; q++) sum[q] += g[q];
    }
    float scalar = pf / ((float)m * 0.01f);
    float4 o;
    o.x = dg[0] + scalar * sum[0]; o.y = dg[1] + scalar * sum[1];
    o.z = dg[2] + scalar * sum[2]; o.w = dg[3] + scalar * sum[3];
    *(float4*)&d_A[kv][idx] = o;
}

// ---- diag core: factor 64x64 in sD (pitch 65), logdet, Z=L^-1 into sZ -----
__device__ void diag_core(int mb, int sidx, int tid, float* sD, float* sZ,
                          float* scr) {
    float* sdinv = scr;
    float* sRed  = scr + 64;
    float* sW8   = scr + 128;
    bool needZ = (sidx < NSTEP - 1);
    if (needZ)
        for (int l = tid; l < NB * 65; l += 256) sZ[l] = 0.f;
    __syncthreads();

#pragma unroll 1
    for (int b = 0; b < NB; b += 8) {
        if (tid == 0) {
            float a[8][8];
#pragma unroll
            for (int i = 0; i < 8; i++)
#pragma unroll
                for (int u = 0; u <= i; u++)
                    a[i][u] = sD[(b + i) * 65 + b + u];
#pragma unroll
            for (int t = 0; t < 8; t++) {
                float rinv = rsqrtf(a[t][t]);
                a[t][t] *= rinv;
                sdinv[b + t] = rinv;
#pragma unroll
                for (int i = t + 1; i < 8; i++) a[i][t] *= rinv;
#pragma unroll
                for (int u = t + 1; u < 8; u++)
#pragma unroll
                    for (int i = u; i < 8; i++)
                        a[i][u] = fmaf(-a[i][t], a[u][t], a[i][u]);
            }
#pragma unroll
            for (int i = 0; i < 8; i++)
#pragma unroll
                for (int u = 0; u <= i; u++)
                    sD[(b + i) * 65 + b + u] = a[i][u];
        }
        __syncthreads();

        int rows = NB - b - 8;
        if (rows > 0) {
            if (tid < rows) {
                int r = b + 8 + tid;
                float x[8];
#pragma unroll
                for (int t = 0; t < 8; t++) x[t] = sD[r * 65 + b + t];
#pragma unroll
                for (int t = 0; t < 8; t++) {
                    float v = x[t];
#pragma unroll
                    for (int u = 0; u < t; u++)
                        v = fmaf(-x[u], sD[(b + t) * 65 + b + u], v);
                    x[t] = v * sdinv[b + t];
                }
#pragma unroll
                for (int t = 0; t < 8; t++) sD[r * 65 + b + t] = x[t];
            }
            __syncthreads();

            int total = rows << 6;
            for (int l = tid; l < total; l += 256) {
                int i = b + 8 + (l >> 6), u = l & 63;
                if (u >= b + 8) {
                    float acc = sD[i * 65 + u];
#pragma unroll
                    for (int t = 0; t < 8; t++)
                        acc = fmaf(-sD[i * 65 + b + t], sD[u * 65 + b + t],
                                   acc);
                    sD[i * 65 + u] = acc;
                }
            }
        }
        __syncthreads();
    }

    if (tid < NB) sRed[tid] = logf(sD[tid * 65 + tid]);
    __syncthreads();
    if (tid < 32) {
        double lsum = (double)sRed[tid] + (double)sRed[tid + 32];
#pragma unroll
        for (int o = 16; o > 0; o >>= 1)
            lsum += __shfl_down_sync(0xffffffffu, lsum, o);
        if (tid == 0) d_hldd[mb] += lsum;
    }
    if (!needZ) return;

    for (int b = 0; b < NB; b += 8) {
        {
            int t0 = tid >> 6;
            int j = tid & 63;
#pragma unroll
            for (int pass = 0; pass < 2; pass++) {
                int t = t0 + pass * 4;
                float acc = 0.f;
                for (int u = 0; u < b; u++)
                    acc = fmaf(sD[(b + t) * 65 + u], sZ[u * 65 + j], acc);
                sW8[t * 64 + j] = acc;
            }
        }
        __syncthreads();
        if (tid < 64) {
            int j = tid;
#pragma unroll
            for (int t = 0; t < 8; t++) {
                int r = b + t;
                if (j <= r) {
                    float v = ((r == j) ? 1.f : 0.f) - sW8[t * 64 + j];
#pragma unroll
                    for (int u = 0; u < 8; u++) {
                        if (u < t)
                            v = fmaf(-sD[r * 65 + b + u], sZ[(b + u) * 65 + j],
                                     v);
                    }
                    sZ[r * 65 + j] = v * sdinv[r];
                }
            }
        }
        __syncthreads();
    }
}

// ---- W GEMM: sWout[t][c] = sum_u Z[t][u] * AT[u][c] -----------------------
__device__ __forceinline__ void w_gemm(const float* sZ, const float* sAT,
                                       float* sWout, int tx, int ty) {
    ull acc2[4][2];
#pragma unroll
    for (int i = 0; i < 4; i++) { acc2[i][0] = 0ull; acc2[i][1] = 0ull; }
#pragma unroll 8
    for (int u = 0; u < NB; u++) {
        float4 bv = *(const float4*)&sAT[u * DP + tx * 4];
        ull b0 = pack2(bv.x, bv.y), b1 = pack2(bv.z, bv.w);
        ull a0 = dup2(sZ[(ty * 4 + 0) * 65 + u]);
        ull a1 = dup2(sZ[(ty * 4 + 1) * 65 + u]);
        ull a2 = dup2(sZ[(ty * 4 + 2) * 65 + u]);
        ull a3 = dup2(sZ[(ty * 4 + 3) * 65 + u]);
        acc2[0][0] = ffma2(a0, b0, acc2[0][0]);
        acc2[0][1] = ffma2(a0, b1, acc2[0][1]);
        acc2[1][0] = ffma2(a1, b0, acc2[1][0]);
        acc2[1][1] = ffma2(a1, b1, acc2[1][1]);
        acc2[2][0] = ffma2(a2, b0, acc2[2][0]);
        acc2[2][1] = ffma2(a2, b1, acc2[2][1]);
        acc2[3][0] = ffma2(a3, b0, acc2[3][0]);
        acc2[3][1] = ffma2(a3, b1, acc2[3][1]);
    }
#pragma unroll
    for (int q = 0; q < 4; q++) {
        float2 lo = unpk2(acc2[q][0]), hi = unpk2(acc2[q][1]);
        float4 v; v.x = lo.x; v.y = lo.y; v.z = hi.x; v.w = hi.y;
        *(float4*)&sWout[(ty * 4 + q) * DP + tx * 4] = v;
    }
}

// ---- transpose-load 64x64 A panel into sAT (pitch DP) ---------------------
__device__ __forceinline__ void at_load(const float* A, int r0, int sc,
                                        float* sAT, int tid) {
    int j = tid >> 2, u0 = (tid & 3) * 16;
    const float* row = &A[(size_t)(r0 + j) * P + sc];
#pragma unroll
    for (int q4 = 0; q4 < 4; q4++) {
        float4 v = *(const float4*)&row[u0 + q4 * 4];
        int u = u0 + q4 * 4;
        sAT[(u + 0) * DP + j] = v.x;
        sAT[(u + 1) * DP + j] = v.y;
        sAT[(u + 2) * DP + j] = v.z;
        sAT[(u + 3) * DP + j] = v.w;
    }
}

// ---- tile GEMM: acc2 = Wi^T * Wj -----------------------------------------
__device__ __forceinline__ void tile_gemm(const float* sWi, const float* sWj,
                                          int tx, int ty, ull acc2[4][2]) {
#pragma unroll
    for (int i = 0; i < 4; i++) { acc2[i][0] = 0ull; acc2[i][1] = 0ull; }
#pragma unroll 8
    for (int t = 0; t < NB; t++) {
        float4 av = *(const float4*)&sWi[t * DP + ty * 4];
        float4 bv = *(const float4*)&sWj[t * DP + tx * 4];
        ull b0 = pack2(bv.x, bv.y), b1 = pack2(bv.z, bv.w);
        ull a0 = dup2(av.x), a1 = dup2(av.y);
        ull a2 = dup2(av.z), a3 = dup2(av.w);
        acc2[0][0] = ffma2(a0, b0, acc2[0][0]);
        acc2[0][1] = ffma2(a0, b1, acc2[0][1]);
        acc2[1][0] = ffma2(a1, b0, acc2[1][0]);
        acc2[1][1] = ffma2(a1, b1, acc2[1][1]);
        acc2[2][0] = ffma2(a2, b0, acc2[2][0]);
        acc2[2][1] = ffma2(a2, b1, acc2[2][1]);
        acc2[3][0] = ffma2(a3, b0, acc2[3][0]);
        acc2[3][1] = ffma2(a3, b1, acc2[3][1]);
    }
}

// ---- k_chol: persistent, shared-W + per-panel flags, 1 barrier/step -------
// smem regions: sZ=fs[0,REG) | sAT=fs[REG,2R) | sWi=[2R,3R) | sWj=[3R,4R)
__global__ __launch_bounds__(256) void k_chol(float* out, int m) {
    int cx = blockIdx.x;
    int mb = blockIdx.y;
    if (mb > d_kval) return;
    extern __shared__ float fs[];
    int tid = threadIdx.x;
    int tx = tid & 15, ty = tid >> 4;
    float* A  = d_A[mb];
    float* Zg = d_Z[mb];

    float* sZ  = fs;
    float* sAT = fs + REG;
    float* sWi = fs + 2 * REG;
    float* sWj = fs + 3 * REG;

    // ---- step 0 diag on CTA0 ----
    if (cx == 0) {
        float* sD = sAT;
        for (int l = tid; l < NB * NB; l += 256) {
            int r = l >> 6, c = l & 63;
            sD[r * 65 + c] = A[(size_t)r * P + c];
        }
        __syncthreads();
        diag_core(mb, 0, tid, sD, sZ, sWj);
        for (int q = tid; q < NB * 65 / 4; q += 256)
            *(float4*)&Zg[q * 4] = *(const float4*)&sZ[q * 4];
    }
    int ep = 1;
    mbar(mb, NCTA * ep); ep++;     // Z(0) ready

    for (int s = 0; s < NSTEP - 1; s++) {
        int nblk = NSTEP - 1 - s;
        int ntile = nblk * (nblk + 1) / 2;
        int sc = s * NB;

        if (cx == 0) {
            // local W0 = Z * A0^T (Z resident), tile00, fused diag(s+1)
            at_load(A, sc + NB, sc, sAT, tid);
            __syncthreads();
            w_gemm(sZ, sAT, sWi, tx, ty);
            __syncthreads();
            ull acc2[4][2];
            tile_gemm(sWi, sWi, tx, ty, acc2);
            float* sD = sAT;
            int r0 = sc + NB;
#pragma unroll
            for (int q = 0; q < 4; q++) {
                float2 lo = unpk2(acc2[q][0]), hi = unpk2(acc2[q][1]);
                const float* row = &A[(size_t)(r0 + ty * 4 + q) * P + r0 + tx * 4];
                float4 v = *(const float4*)row;
                int rr = ty * 4 + q, cc = tx * 4;
                sD[rr * 65 + cc + 0] = v.x - lo.x;
                sD[rr * 65 + cc + 1] = v.y - lo.y;
                sD[rr * 65 + cc + 2] = v.z - hi.x;
                sD[rr * 65 + cc + 3] = v.w - hi.y;
            }
            __syncthreads();
            diag_core(mb, s + 1, tid, sD, sZ, sWj);
            if (s + 1 < NSTEP - 1) {
                for (int q = tid; q < NB * 65 / 4; q += 256)
                    *(float4*)&Zg[q * 4] = *(const float4*)&sZ[q * 4];
            }
        } else {
            // producer role: CTA cx (1..nblk) computes + publishes W_{cx-1}
            if (cx <= nblk) {
                for (int q = tid; q < NB * 65 / 4; q += 256)
                    *(float4*)&sZ[q * 4] = *(const float4*)&Zg[q * 4];
                int panel = cx - 1;
                at_load(A, sc + NB + panel * NB, sc, sAT, tid);
                __syncthreads();
                w_gemm(sZ, sAT, sWi, tx, ty);
                __syncthreads();
                float* Wg = d_W[mb][panel];
                for (int q = tid; q < NB * DP / 4; q += 256)
                    *(float4*)&Wg[q * 4] = *(const float4*)&sWi[q * 4];
                __syncthreads();
                if (tid == 0) rel_st(&d_wflag[mb][panel], s + 1);
            }
            // consumer role: tiles l = cx, cx+(NCTA-1), ...  (l >= 1)
            for (int l = cx; l < ntile; l += NCTA - 1) {
                int ti = 0;
                while ((ti + 1) * (ti + 2) / 2 <= l) ti++;
                int tj = l - ti * (ti + 1) / 2;
                int ri = sc + NB + ti * NB, rj = sc + NB + tj * NB;

                __syncthreads();
                wflag_wait(mb, ti, s + 1);
                {
                    const float* Wg = d_W[mb][ti];
                    for (int q = tid; q < NB * DP / 4; q += 256)
                        *(float4*)&sWi[q * 4] = *(const float4*)&Wg[q * 4];
                }
                const float* pWj = sWi;
                if (ti != tj) {
                    wflag_wait(mb, tj, s + 1);
                    const float* Wg = d_W[mb][tj];
                    for (int q = tid; q < NB * DP / 4; q += 256)
                        *(float4*)&sWj[q * 4] = *(const float4*)&Wg[q * 4];
                    pWj = sWj;
                }
                __syncthreads();
                ull acc2[4][2];
                tile_gemm(sWi, pWj, tx, ty, acc2);
#pragma unroll
                for (int q = 0; q < 4; q++) {
                    float2 lo = unpk2(acc2[q][0]), hi = unpk2(acc2[q][1]);
                    float* row = &A[(size_t)(ri + ty * 4 + q) * P + rj + tx * 4];
                    float4 v = *(float4*)row;
                    v.x -= lo.x; v.y -= lo.y; v.z -= hi.x; v.w -= hi.y;
                    *(float4*)row = v;
                }
            }
        }
        mbar(mb, NCTA * ep); ep++;     // trailing + Z(s+1) ready
    }

    // ---- finalize ----
    if (cx == 0 && tid == 0) {
        rel_add(&d_done);
        if (mb == 0) {
            int kv = d_kval;
            while (acq_ld(&d_done) < kv + 1) { }
            double comp = 0.0;
            for (int j = 0; j < kv; j++) {
                double trPi = (double)d_cnt[j] + 1e-8;
                comp += d_hldd[j] * trPi / (double)m;
            }
            out[0] = (float)d_hldd[kv];
            out[1] = (float)comp;
            d_lbar = 0;   // reset labels barrier for next graph replay
        }
    }
}

// ---------------- launch ----------------------------------------------------
extern "C" void kernel_launch(void* const* d_in, const int* in_sizes, int n_in,
                              void* d_out, int out_size) {
    const float* X    = (const float*)d_in[0];
    const void*  Y    = d_in[1];
    const int*   ncls = (n_in >= 3) ? (const int*)d_in[2] : nullptr;
    int m = in_sizes[1];
    int p = in_sizes[0] / m;          // 512
    float* out = (float*)d_out;
    (void)out_size;
    int nchunk = (m + 255) / 256;

    cudaFuncSetAttribute(k_chol, cudaFuncAttributeMaxDynamicSharedMemorySize,
                         FT_SMEM_BYTES);

    k_labels<<<nchunk, 256>>>(Y, ncls, m, nchunk);
    k_gram<<<dim3(10, K_MAX, NSLICE), 256>>>(X, p);
    k_assemble<<<(P * P / 4 + 255) / 256, 256>>>(m, (float)p);
    k_chol<<<dim3(NCTA, NM), 256, FT_SMEM_BYTES>>>(out, m);
}

// round 14
// speedup vs baseline: 1.4691x; 1.0060x over previous
#include <cuda_runtime.h>
#include <math.h>

#define P       512
#define K_MAX   16
#define NM      (K_MAX + 1)
#define M_CAP   65536
#define NCH_MAX 256
#define NB      64
#define NSTEP   (P / NB)      // 8
#define NSLICE  3
#define DP      68
#define NCTA    15
#define REG     4352          // smem region stride (floats)

#define FT_SMEM_BYTES (4 * REG * 4)   // 69632 B

typedef unsigned long long ull;

// ---------------- f32x2 packed helpers (Blackwell sm_103a) -----------------
__device__ __forceinline__ ull ffma2(ull a, ull b, ull c) {
    ull d;
    asm("fma.rn.f32x2 %0, %1, %2, %3;" : "=l"(d) : "l"(a), "l"(b), "l"(c));
    return d;
}
__device__ __forceinline__ ull dup2(float x) {
    ull r; unsigned xb = __float_as_uint(x);
    asm("mov.b64 %0, {%1, %2};" : "=l"(r) : "r"(xb), "r"(xb));
    return r;
}
__device__ __forceinline__ ull pack2(float lo, float hi) {
    ull r;
    asm("mov.b64 %0, {%1, %2};" : "=l"(r) : "f"(lo), "f"(hi));
    return r;
}
__device__ __forceinline__ float2 unpk2(ull v) {
    float2 r;
    asm("mov.b64 {%0, %1}, %2;" : "=f"(r.x), "=f"(r.y) : "l"(v));
    return r;
}

// ---------------- device scratch -------------------------------------------
__device__ int    d_cnt[K_MAX];
__device__ int    d_kval;
__device__ int    d_idx[M_CAP];
__device__ int    d_bh[NCH_MAX][K_MAX];
__device__ int    d_boff[NCH_MAX][K_MAX];
__device__ int    d_cstart[K_MAX];
__device__ int    d_lbar;
__device__ int    d_done;
__device__ int    d_zflag[NM];
__device__ int    d_wflag[NM][NSTEP - 1];
__device__ int    d_tflag[NM][64];            // [I*8+J] update counts
__device__ float  d_Gk[NSLICE][K_MAX][P * P];
__device__ float  d_A[NM][P * P];
__device__ float  d_Z[NSTEP][NM][NB * 65];    // step-indexed, no reuse
__device__ float  d_W[NSTEP - 1][NM][NSTEP - 1][NB * DP];
__device__ double d_hldd[NM];

// ---------------- release/acquire primitives -------------------------------
__device__ __forceinline__ void rel_add(int* p) {
    int d;
    asm volatile("atom.release.gpu.add.s32 %0, [%1], 1;"
                 : "=r"(d) : "l"(p) : "memory");
}
__device__ __forceinline__ void rel_st(int* p, int v) {
    asm volatile("st.release.gpu.s32 [%0], %1;" :: "l"(p), "r"(v) : "memory");
}
__device__ __forceinline__ int acq_ld(const int* p) {
    int v;
    asm volatile("ld.acquire.gpu.s32 %0, [%1];" : "=r"(v) : "l"(p) : "memory");
    return v;
}
__device__ __forceinline__ void gbar(int nb, int ep) {
    __syncthreads();
    if (threadIdx.x == 0) {
        rel_add(&d_lbar);
        while (acq_ld(&d_lbar) < nb * ep) { }
    }
    __syncthreads();
}
// wait up to 3 flags (tid0 spins, then block sync)
__device__ __forceinline__ void fwait3(const int* p0, int v0,
                                       const int* p1, int v1,
                                       const int* p2, int v2) {
    if (threadIdx.x == 0) {
        if (p0) while (acq_ld(p0) < v0) { }
        if (p1) while (acq_ld(p1) < v1) { }
        if (p2) while (acq_ld(p2) < v2) { }
    }
    __syncthreads();
}

// ------- k_labels: dtype detect + hist + scan + stable scatter -------------
__global__ __launch_bounds__(256) void k_labels(const void* __restrict__ Y,
                                                const int* ncls, int m,
                                                int nchunk) {
    __shared__ int sh[K_MAX];
    __shared__ int swh[8 * K_MAX];
    __shared__ int nzf;
    int tid = threadIdx.x;
    int b = blockIdx.x;
    if (tid == 0) nzf = 0;
    if (tid < K_MAX) sh[tid] = 0;
    __syncthreads();

    int lim = m / 2; if (lim > 512) lim = 512;
    int found = 0;
    for (int i = tid; i < lim; i += 256)
        if (((const int*)Y)[2 * i + 1] != 0) found = 1;
    if (__any_sync(0xffffffffu, found)) {
        if ((tid & 31) == 0) atomicOr(&nzf, 1);
    }
    __syncthreads();
    int is64 = nzf ? 0 : 1;

    int i = b * 256 + tid;
    int c = -1;
    if (i < m) {
        c = is64 ? (int)((const long long*)Y)[i] : ((const int*)Y)[i];
        if (c < 0 || c >= K_MAX) c = 0;
        atomicAdd(&sh[c], 1);
    }
    __syncthreads();
    if (tid < K_MAX) d_bh[b][tid] = sh[tid];

    gbar(nchunk, 1);

    if (b == 0) {
        if (tid < K_MAX) {
            int run = 0;
            for (int bb = 0; bb < nchunk; bb++) {
                d_boff[bb][tid] = run;
                run += d_bh[bb][tid];
            }
            d_cnt[tid] = run;
            sh[tid] = run;
        }
        __syncthreads();
        if (tid == 0) {
            int run = 0;
            for (int cc = 0; cc < K_MAX; cc++) {
                d_cstart[cc] = run;
                run += sh[cc];
            }
            int k = ncls ? *ncls : 10;
            if (k < 1) k = 1;
            if (k > K_MAX) k = K_MAX;
            d_kval = k;
            d_done = 0;
        }
        if (tid < NM) { d_hldd[tid] = 0.0; d_zflag[tid] = 0; }
        for (int q = tid; q < NM * (NSTEP - 1); q += 256)
            ((int*)d_wflag)[q] = 0;
        for (int q = tid; q < NM * 64; q += 256)
            ((int*)d_tflag)[q] = 0;
    }

    gbar(nchunk, 2);

    if (tid < 8 * K_MAX) swh[tid] = 0;
    __syncthreads();
    int lane = tid & 31, w = tid >> 5;
    unsigned mask = __match_any_sync(0xffffffffu, c);
    int rin = __popc(mask & ((1u << lane) - 1u));
    int leader = __ffs(mask) - 1;
    if (c >= 0 && lane == leader) swh[w * K_MAX + c] = __popc(mask);
    __syncthreads();
    if (c >= 0) {
        int pre = 0;
        for (int w2 = 0; w2 < w; w2++) pre += swh[w2 * K_MAX + c];
        d_idx[d_cstart[c] + d_boff[b][c] + pre + rin] = i;
    }
}

// ------- per-class Gram: dense gather over sorted class range --------------
__global__ __launch_bounds__(256) void k_gram(const float* __restrict__ X,
                                              int p) {
    int c = blockIdx.y;
    if (c >= d_kval) return;
    int tile = blockIdx.x;
    int ti = 0;
    while ((ti + 1) * (ti + 2) / 2 <= tile) ti++;
    int tj = tile - ti * (ti + 1) / 2;
    int a0 = ti * 128, b0 = tj * 128;
    int z = blockIdx.z;
    int cstart = d_cstart[c], ccnt = d_cnt[c];
    int sb = (int)((long long)ccnt * z / NSLICE);
    int se = (int)((long long)ccnt * (z + 1) / NSLICE);

    __shared__ __align__(16) float sA[32][132];
    __shared__ __align__(16) float sB[32][132];
    __shared__ int sidx[32];

    int tid = threadIdx.x;
    int tx = tid & 15, ty = tid >> 4;
    int lt = tid >> 3, lc = tid & 7;

    ull acc2[8][4];
#pragma unroll
    for (int i = 0; i < 8; i++)
#pragma unroll
        for (int q = 0; q < 4; q++) acc2[i][q] = 0ull;

    for (int base = sb; base < se; base += 32) {
        int nv = se - base;
        if (nv > 32) nv = 32;
        __syncthreads();
        if (tid < 32)
            sidx[tid] = (tid < nv) ? d_idx[cstart + base + tid] : -1;
        __syncthreads();
        {
            int s = sidx[lt];
            if (s >= 0) {
                const float* xr = X + (size_t)s * p;
#pragma unroll
                for (int q = 0; q < 4; q++) {
                    int col = lc * 16 + q * 4;
                    *(float4*)&sA[lt][col] = *(const float4*)&xr[a0 + col];
                    *(float4*)&sB[lt][col] = *(const float4*)&xr[b0 + col];
                }
            }
        }
        __syncthreads();

        for (int t = 0; t < nv; t++) {
            float a[8];
            ull ad[8], b2[4];
            *(float4*)&a[0] = *(const float4*)&sA[t][ty * 8];
            *(float4*)&a[4] = *(const float4*)&sA[t][ty * 8 + 4];
#pragma unroll
            for (int i = 0; i < 8; i++) ad[i] = dup2(a[i]);
#pragma unroll
            for (int q = 0; q < 4; q++)
                b2[q] = *(const ull*)&sB[t][tx * 2 + q * 32];
#pragma unroll
            for (int i = 0; i < 8; i++)
#pragma unroll
                for (int q = 0; q < 4; q++)
                    acc2[i][q] = ffma2(ad[i], b2[q], acc2[i][q]);
        }
    }

    float* G = d_Gk[z][c];
    int gi = a0 + ty * 8;
#pragma unroll
    for (int i = 0; i < 8; i++)
#pragma unroll
        for (int q = 0; q < 4; q++) {
            float2 v = unpk2(acc2[i][q]);
            int col = b0 + q * 32 + tx * 2;
            *(float2*)&G[(size_t)(gi + i) * P + col] = v;
        }
    if (ti != tj) {
#pragma unroll
        for (int i = 0; i < 8; i++)
#pragma unroll
            for (int q = 0; q < 4; q++) {
                float2 v = unpk2(acc2[i][q]);
                int col = b0 + q * 32 + tx * 2;
                G[(size_t)col * P + gi + i]       = v.x;
                G[(size_t)(col + 1) * P + gi + i] = v.y;
            }
    }
}

// --------- assemble ---------------------------------------------------------
__global__ __launch_bounds__(256) void k_assemble(int m, float pf) {
    int idx4 = blockIdx.x * blockDim.x + threadIdx.x;
    if (idx4 >= P * P / 4) return;
    int idx = idx4 * 4;
    int r = idx >> 9, c0 = idx & 511;
    int kv = d_kval;
    float dg[4];
#pragma unroll
    for (int q = 0; q < 4; q++) dg[q] = (r == c0 + q) ? 1.f : 0.f;
    float sum[4] = {0.f, 0.f, 0.f, 0.f};
    for (int j = 0; j < kv; j++) {
        float4 g0 = *(const float4*)&d_Gk[0][j][idx];
        float4 g1 = *(const float4*)&d_Gk[1][j][idx];
        float4 g2 = *(const float4*)&d_Gk[2][j][idx];
        float g[4];
        g[0] = g0.x + g1.x + g2.x; g[1] = g0.y + g1.y + g2.y;
        g[2] = g0.z + g1.z + g2.z; g[3] = g0.w + g1.w + g2.w;
        float scal = pf / (((float)d_cnt[j] + 1e-8f) * 0.01f);
        float4 o;
        o.x = dg[0] + scal * g[0]; o.y = dg[1] + scal * g[1];
        o.z = dg[2] + scal * g[2]; o.w = dg[3] + scal * g[3];
        *(float4*)&d_A[j][idx] = o;
#pragma unroll
        for (int q = 0; q < 4; q++) sum[q] += g[q];
    }
    float scalar = pf / ((float)m * 0.01f);
    float4 o;
    o.x = dg[0] + scalar * sum[0]; o.y = dg[1] + scalar * sum[1];
    o.z = dg[2] + scalar * sum[2]; o.w = dg[3] + scalar * sum[3];
    *(float4*)&d_A[kv][idx] = o;
}

// ---- diag core: factor 64x64 in sD (pitch 65, lower), logdet, Z=L^-1 ------
__device__ void diag_core(int mb, int sidx, int tid, float* sD, float* sZ,
                          float* scr) {
    float* sdinv = scr;
    float* sRed  = scr + 64;
    float* sW8   = scr + 128;
    bool needZ = (sidx < NSTEP - 1);
    if (needZ)
        for (int l = tid; l < NB * 65; l += 256) sZ[l] = 0.f;
    __syncthreads();

#pragma unroll 1
    for (int b = 0; b < NB; b += 8) {
        if (tid == 0) {
            float a[8][8];
#pragma unroll
            for (int i = 0; i < 8; i++)
#pragma unroll
                for (int u = 0; u <= i; u++)
                    a[i][u] = sD[(b + i) * 65 + b + u];
#pragma unroll
            for (int t = 0; t < 8; t++) {
                float rinv = rsqrtf(a[t][t]);
                a[t][t] *= rinv;
                sdinv[b + t] = rinv;
#pragma unroll
                for (int i = t + 1; i < 8; i++) a[i][t] *= rinv;
#pragma unroll
                for (int u = t + 1; u < 8; u++)
#pragma unroll
                    for (int i = u; i < 8; i++)
                        a[i][u] = fmaf(-a[i][t], a[u][t], a[i][u]);
            }
#pragma unroll
            for (int i = 0; i < 8; i++)
#pragma unroll
                for (int u = 0; u <= i; u++)
                    sD[(b + i) * 65 + b + u] = a[i][u];
        }
        __syncthreads();

        int rows = NB - b - 8;
        if (rows > 0) {
            if (tid < rows) {
                int r = b + 8 + tid;
                float x[8];
#pragma unroll
                for (int t = 0; t < 8; t++) x[t] = sD[r * 65 + b + t];
#pragma unroll
                for (int t = 0; t < 8; t++) {
                    float v = x[t];
#pragma unroll
                    for (int u = 0; u < t; u++)
                        v = fmaf(-x[u], sD[(b + t) * 65 + b + u], v);
                    x[t] = v * sdinv[b + t];
                }
#pragma unroll
                for (int t = 0; t < 8; t++) sD[r * 65 + b + t] = x[t];
            }
            __syncthreads();

            // rank-8 update, LOWER TRIANGLE ONLY (all later reads are lower)
            int total = rows << 6;
            for (int l = tid; l < total; l += 256) {
                int i = b + 8 + (l >> 6), u = l & 63;
                if (u >= b + 8 && u <= i) {
                    float acc = sD[i * 65 + u];
#pragma unroll
                    for (int t = 0; t < 8; t++)
                        acc = fmaf(-sD[i * 65 + b + t], sD[u * 65 + b + t],
                                   acc);
                    sD[i * 65 + u] = acc;
                }
            }
        }
        __syncthreads();
    }

    if (tid < NB) sRed[tid] = logf(sD[tid * 65 + tid]);
    __syncthreads();
    if (tid < 32) {
        double lsum = (double)sRed[tid] + (double)sRed[tid + 32];
#pragma unroll
        for (int o = 16; o > 0; o >>= 1)
            lsum += __shfl_down_sync(0xffffffffu, lsum, o);
        if (tid == 0) d_hldd[mb] += lsum;
    }
    if (!needZ) return;

    for (int b = 0; b < NB; b += 8) {
        {
            int t0 = tid >> 6;
            int j = tid & 63;
#pragma unroll
            for (int pass = 0; pass < 2; pass++) {
                int t = t0 + pass * 4;
                float acc = 0.f;
                for (int u = 0; u < b; u++)
                    acc = fmaf(sD[(b + t) * 65 + u], sZ[u * 65 + j], acc);
                sW8[t * 64 + j] = acc;
            }
        }
        __syncthreads();
        if (tid < 64) {
            int j = tid;
#pragma unroll
            for (int t = 0; t < 8; t++) {
                int r = b + t;
                if (j <= r) {
                    float v = ((r == j) ? 1.f : 0.f) - sW8[t * 64 + j];
#pragma unroll
                    for (int u = 0; u < 8; u++) {
                        if (u < t)
                            v = fmaf(-sD[r * 65 + b + u], sZ[(b + u) * 65 + j],
                                     v);
                    }
                    sZ[r * 65 + j] = v * sdinv[r];
                }
            }
        }
        __syncthreads();
    }
}

// ---- W GEMM: sWout[t][c] = sum_u Z[t][u] * AT[u][c] -----------------------
__device__ __forceinline__ void w_gemm(const float* sZ, const float* sAT,
                                       float* sWout, int tx, int ty) {
    ull acc2[4][2];
#pragma unroll
    for (int i = 0; i < 4; i++) { acc2[i][0] = 0ull; acc2[i][1] = 0ull; }
#pragma unroll 8
    for (int u = 0; u < NB; u++) {
        float4 bv = *(const float4*)&sAT[u * DP + tx * 4];
        ull b0 = pack2(bv.x, bv.y), b1 = pack2(bv.z, bv.w);
        ull a0 = dup2(sZ[(ty * 4 + 0) * 65 + u]);
        ull a1 = dup2(sZ[(ty * 4 + 1) * 65 + u]);
        ull a2 = dup2(sZ[(ty * 4 + 2) * 65 + u]);
        ull a3 = dup2(sZ[(ty * 4 + 3) * 65 + u]);
        acc2[0][0] = ffma2(a0, b0, acc2[0][0]);
        acc2[0][1] = ffma2(a0, b1, acc2[0][1]);
        acc2[1][0] = ffma2(a1, b0, acc2[1][0]);
        acc2[1][1] = ffma2(a1, b1, acc2[1][1]);
        acc2[2][0] = ffma2(a2, b0, acc2[2][0]);
        acc2[2][1] = ffma2(a2, b1, acc2[2][1]);
        acc2[3][0] = ffma2(a3, b0, acc2[3][0]);
        acc2[3][1] = ffma2(a3, b1, acc2[3][1]);
    }
#pragma unroll
    for (int q = 0; q < 4; q++) {
        float2 lo = unpk2(acc2[q][0]), hi = unpk2(acc2[q][1]);
        float4 v; v.x = lo.x; v.y = lo.y; v.z = hi.x; v.w = hi.y;
        *(float4*)&sWout[(ty * 4 + q) * DP + tx * 4] = v;
    }
}

__device__ __forceinline__ void at_load(const float* A, int r0, int sc,
                                        float* sAT, int tid) {
    int j = tid >> 2, u0 = (tid & 3) * 16;
    const float* row = &A[(size_t)(r0 + j) * P + sc];
#pragma unroll
    for (int q4 = 0; q4 < 4; q4++) {
        float4 v = *(const float4*)&row[u0 + q4 * 4];
        int u = u0 + q4 * 4;
        sAT[(u + 0) * DP + j] = v.x;
        sAT[(u + 1) * DP + j] = v.y;
        sAT[(u + 2) * DP + j] = v.z;
        sAT[(u + 3) * DP + j] = v.w;
    }
}

__device__ __forceinline__ void tile_gemm(const float* sWi, const float* sWj,
                                          int tx, int ty, ull acc2[4][2]) {
#pragma unroll
    for (int i = 0; i < 4; i++) { acc2[i][0] = 0ull; acc2[i][1] = 0ull; }
#pragma unroll 8
    for (int t = 0; t < NB; t++) {
        float4 av = *(const float4*)&sWi[t * DP + ty * 4];
        float4 bv = *(const float4*)&sWj[t * DP + tx * 4];
        ull b0 = pack2(bv.x, bv.y), b1 = pack2(bv.z, bv.w);
        ull a0 = dup2(av.x), a1 = dup2(av.y);
        ull a2 = dup2(av.z), a3 = dup2(av.w);
        acc2[0][0] = ffma2(a0, b0, acc2[0][0]);
        acc2[0][1] = ffma2(a0, b1, acc2[0][1]);
        acc2[1][0] = ffma2(a1, b0, acc2[1][0]);
        acc2[1][1] = ffma2(a1, b1, acc2[1][1]);
        acc2[2][0] = ffma2(a2, b0, acc2[2][0]);
        acc2[2][1] = ffma2(a2, b1, acc2[2][1]);
        acc2[3][0] = ffma2(a3, b0, acc2[3][0]);
        acc2[3][1] = ffma2(a3, b1, acc2[3][1]);
    }
}

// ---- k_chol: persistent, pure dataflow (no step barrier) ------------------
// smem regions: sZ=fs[0,REG) | sAT=fs[REG,2R) | sWi=[2R,3R) | sWj=[3R,4R)
__global__ __launch_bounds__(256) void k_chol(float* out, int m) {
    int cx = blockIdx.x;
    int mb = blockIdx.y;
    if (mb > d_kval) return;
    extern __shared__ float fs[];
    int tid = threadIdx.x;
    int tx = tid & 15, ty = tid >> 4;
    float* A = d_A[mb];

    float* sZ  = fs;
    float* sAT = fs + REG;
    float* sWi = fs + 2 * REG;
    float* sWj = fs + 3 * REG;
    int* tfl = d_tflag[mb];

    if (cx == 0) {
        // ---- CTA0: the critical chain, pure dataflow ----
        {
            float* sD = sAT;
            for (int l = tid; l < NB * NB; l += 256) {
                int r = l >> 6, c = l & 63;
                sD[r * 65 + c] = A[(size_t)r * P + c];
            }
            __syncthreads();
            diag_core(mb, 0, tid, sD, sZ, sWj);
            float* Zg = d_Z[0][mb];
            for (int q = tid; q < NB * 65 / 4; q += 256)
                *(float4*)&Zg[q * 4] = *(const float4*)&sZ[q * 4];
            __syncthreads();
            if (tid == 0) rel_st(&d_zflag[mb], 1);
        }
        for (int s = 0; s < NSTEP - 1; s++) {
            int sc = s * NB;
            // need blocks (s+1,s) and (s+1,s+1) updated through step s-1
            fwait3(&tfl[(s + 1) * 8 + s], s, &tfl[(s + 1) * 8 + s + 1], s,
                   0, 0);
            at_load(A, sc + NB, sc, sAT, tid);
            __syncthreads();
            w_gemm(sZ, sAT, sWi, tx, ty);
            __syncthreads();
            ull acc2[4][2];
            tile_gemm(sWi, sWi, tx, ty, acc2);
            float* sD = sAT;
            int r0 = sc + NB;
#pragma unroll
            for (int q = 0; q < 4; q++) {
                float2 lo = unpk2(acc2[q][0]), hi = unpk2(acc2[q][1]);
                const float* row =
                    &A[(size_t)(r0 + ty * 4 + q) * P + r0 + tx * 4];
                float4 v = *(const float4*)row;
                int rr = ty * 4 + q, cc = tx * 4;
                sD[rr * 65 + cc + 0] = v.x - lo.x;
                sD[rr * 65 + cc + 1] = v.y - lo.y;
                sD[rr * 65 + cc + 2] = v.z - hi.x;
                sD[rr * 65 + cc + 3] = v.w - hi.y;
            }
            __syncthreads();
            diag_core(mb, s + 1, tid, sD, sZ, sWj);
            if (s + 1 < NSTEP - 1) {
                float* Zg = d_Z[s + 1][mb];
                for (int q = tid; q < NB * 65 / 4; q += 256)
                    *(float4*)&Zg[q * 4] = *(const float4*)&sZ[q * 4];
                __syncthreads();
                if (tid == 0) rel_st(&d_zflag[mb], s + 2);
            }
        }
        // finalize
        if (tid == 0) {
            rel_add(&d_done);
            if (mb == 0) {
                int kv = d_kval;
                while (acq_ld(&d_done) < kv + 1) { }
                double comp = 0.0;
                for (int j = 0; j < kv; j++) {
                    double trPi = (double)d_cnt[j] + 1e-8;
                    comp += d_hldd[j] * trPi / (double)m;
                }
                out[0] = (float)d_hldd[kv];
                out[1] = (float)comp;
                d_lbar = 0;
            }
        }
        return;
    }

    // ---- workers: producer + consumer roles, flag-driven ----
    for (int s = 0; s < NSTEP - 1; s++) {
        int nblk = NSTEP - 1 - s;
        int ntile = nblk * (nblk + 1) / 2;
        int sc = s * NB;

        if (cx <= nblk && nblk > 1) {
            int panel = cx - 1;
            // need Z(s) and A block (s+1+panel, s) through step s-1
            fwait3(&d_zflag[mb], s + 1,
                   &tfl[(s + 1 + panel) * 8 + s], s, 0, 0);
            {
                const float* Zg = d_Z[s][mb];
                for (int q = tid; q < NB * 65 / 4; q += 256)
                    *(float4*)&sZ[q * 4] = *(const float4*)&Zg[q * 4];
            }
            at_load(A, sc + NB + panel * NB, sc, sAT, tid);
            __syncthreads();
            w_gemm(sZ, sAT, sWi, tx, ty);
            __syncthreads();
            float* Wg = d_W[s][mb][panel];
            for (int q = tid; q < NB * DP / 4; q += 256)
                *(float4*)&Wg[q * 4] = *(const float4*)&sWi[q * 4];
            __syncthreads();
            if (tid == 0) rel_st(&d_wflag[mb][panel], s + 1);
        }

        for (int l = cx; l < ntile; l += NCTA - 1) {
            int ti = 0;
            while ((ti + 1) * (ti + 2) / 2 <= l) ti++;
            int tj = l - ti * (ti + 1) / 2;
            int ri = sc + NB + ti * NB, rj = sc + NB + tj * NB;
            int I = s + 1 + ti, J = s + 1 + tj;

            __syncthreads();
            fwait3(&d_wflag[mb][ti], s + 1,
                   (ti != tj) ? &d_wflag[mb][tj] : 0, s + 1,
                   &tfl[I * 8 + J], s);
            {
                const float* Wg = d_W[s][mb][ti];
                for (int q = tid; q < NB * DP / 4; q += 256)
                    *(float4*)&sWi[q * 4] = *(const float4*)&Wg[q * 4];
            }
            const float* pWj = sWi;
            if (ti != tj) {
                const float* Wg = d_W[s][mb][tj];
                for (int q = tid; q < NB * DP / 4; q += 256)
                    *(float4*)&sWj[q * 4] = *(const float4*)&Wg[q * 4];
                pWj = sWj;
            }
            __syncthreads();
            ull acc2[4][2];
            tile_gemm(sWi, pWj, tx, ty, acc2);
#pragma unroll
            for (int q = 0; q < 4; q++) {
                float2 lo = unpk2(acc2[q][0]), hi = unpk2(acc2[q][1]);
                float* row = &A[(size_t)(ri + ty * 4 + q) * P + rj + tx * 4];
                float4 v = *(float4*)row;
                v.x -= lo.x; v.y -= lo.y; v.z -= hi.x; v.w -= hi.y;
                *(float4*)row = v;
            }
            __syncthreads();
            if (tid == 0) rel_st(&tfl[I * 8 + J], s + 1);
        }
    }
}

// ---------------- launch ----------------------------------------------------
extern "C" void kernel_launch(void* const* d_in, const int* in_sizes, int n_in,
                              void* d_out, int out_size) {
    const float* X    = (const float*)d_in[0];
    const void*  Y    = d_in[1];
    const int*   ncls = (n_in >= 3) ? (const int*)d_in[2] : nullptr;
    int m = in_sizes[1];
    int p = in_sizes[0] / m;          // 512
    float* out = (float*)d_out;
    (void)out_size;
    int nchunk = (m + 255) / 256;

    cudaFuncSetAttribute(k_chol, cudaFuncAttributeMaxDynamicSharedMemorySize,
                         FT_SMEM_BYTES);

    k_labels<<<nchunk, 256>>>(Y, ncls, m, nchunk);
    k_gram<<<dim3(10, K_MAX, NSLICE), 256>>>(X, p);
    k_assemble<<<(P * P / 4 + 255) / 256, 256>>>(m, (float)p);
    k_chol<<<dim3(NCTA, NM), 256, FT_SMEM_BYTES>>>(out, m);
}